// round 1
// baseline (speedup 1.0000x reference)
#include <cuda_runtime.h>
#include <cstddef>

// ---------------------------------------------------------------------------
// Problem constants: B=8, N=M=128, H=512, D=2H=1024
// ---------------------------------------------------------------------------
#define BB   8
#define NN   128
#define HH   512
#define DD   1024

// Scratch layout (floats)
#define SZ_PROJ (BB*NN*HH)      // 524288
#define SZ_XB   (BB*NN*DD)      // 1048576
#define SZ_S    (BB*NN*NN)      // 131072
#define SZ_SD   (BB*NN*4*NN)    // 524288
#define SZ_AGG  (BB*NN*2*DD)    // 2097152

#define OFF_XC  0
#define OFF_YC  (OFF_XC + SZ_PROJ)
#define OFF_XM  (OFF_YC + SZ_PROJ)
#define OFF_YM  (OFF_XM + SZ_PROJ)
#define OFF_XB  (OFF_YM + SZ_PROJ)
#define OFF_SC  (OFF_XB + SZ_XB)
#define OFF_SB  (OFF_SC + SZ_S)
#define OFF_SMN (OFF_SB + SZ_S)
#define OFF_SD1 (OFF_SMN + SZ_S)
#define OFF_SD2 (OFF_SD1 + SZ_SD)
#define OFF_AGG (OFF_SD2 + SZ_SD)
#define OFF_W1V (OFF_AGG + SZ_AGG)
#define SCRATCH_TOTAL (OFF_W1V + 2*DD)

__device__ float g_scratch[SCRATCH_TOTAL];

// tanh(x) = 1 - 2/(exp(2x)+1); abs error <= ~1e-7, saturates correctly at +-1.
__device__ __forceinline__ float ftanh(float x) {
    float e = __expf(2.0f * x);
    return 1.0f - __fdividef(2.0f, e + 1.0f);
}

// ---------------------------------------------------------------------------
// Generic fp32 GEMM: C[M,N] = A[M,K] @ W[K,N], all row-major.
// BM=BN=64, BK=16, 256 threads, 4x4 per thread. M,N multiples of 64, K of 16.
// ---------------------------------------------------------------------------
__global__ __launch_bounds__(256) void gemm_nn(
    const float* __restrict__ A, const float* __restrict__ W,
    float* __restrict__ C, int M, int K, int N)
{
    __shared__ float As[16][68];
    __shared__ float Bs[16][68];
    const int bm = blockIdx.y * 64, bn = blockIdx.x * 64;
    const int t = threadIdx.x;
    const int tx = t & 15, ty = t >> 4;

    float acc[4][4];
#pragma unroll
    for (int i = 0; i < 4; i++)
#pragma unroll
        for (int j = 0; j < 4; j++) acc[i][j] = 0.0f;

    for (int k0 = 0; k0 < K; k0 += 16) {
#pragma unroll
        for (int i = 0; i < 4; i++) {
            int idx = t + i * 256;           // 0..1023
            int r = idx >> 4, c = idx & 15;  // A: 64 rows x 16 cols
            As[c][r] = A[(size_t)(bm + r) * K + k0 + c];
        }
#pragma unroll
        for (int i = 0; i < 4; i++) {
            int idx = t + i * 256;
            int r = idx >> 6, c = idx & 63;  // W: 16 rows x 64 cols
            Bs[r][c] = W[(size_t)(k0 + r) * N + bn + c];
        }
        __syncthreads();
#pragma unroll
        for (int k = 0; k < 16; k++) {
            float a[4], bv[4];
#pragma unroll
            for (int i = 0; i < 4; i++) a[i] = As[k][ty * 4 + i];
#pragma unroll
            for (int j = 0; j < 4; j++) bv[j] = Bs[k][tx * 4 + j];
#pragma unroll
            for (int i = 0; i < 4; i++)
#pragma unroll
                for (int j = 0; j < 4; j++)
                    acc[i][j] = fmaf(a[i], bv[j], acc[i][j]);
        }
        __syncthreads();
    }
#pragma unroll
    for (int i = 0; i < 4; i++)
#pragma unroll
        for (int j = 0; j < 4; j++)
            C[(size_t)(bm + ty * 4 + i) * N + bn + tx * 4 + j] = acc[i][j];
}

// ---------------------------------------------------------------------------
// Fused dot-attention scores (the dominant ~137 GF each):
//   spart[b][m][hc][n] = sum_{h in chunk hc} v_h * tanh( sum_d x[b,n,d]*y[b,m,d]*W[d,h] )
// grid (4 h-chunks, 128 m, 8 b), 256 threads, 128x128 tile, 8x8 per thread.
// ---------------------------------------------------------------------------
__global__ __launch_bounds__(256) void dot_scores(
    const float* __restrict__ x, const float* __restrict__ y,
    const float* __restrict__ W, const float* __restrict__ v,
    float* __restrict__ spart)
{
    const int hc = blockIdx.x;
    const int m  = blockIdx.y;
    const int b  = blockIdx.z;
    const int h0 = hc * 128;
    const int t  = threadIdx.x;

    __shared__ __align__(16) float ys[DD];
    __shared__ __align__(16) float As[16][132];
    __shared__ __align__(16) float Bs[16][132];
    __shared__ float red[16][16][8];

    {   // y[b][m][:] -> smem
        const float4* yp = (const float4*)(y + ((size_t)b * NN + m) * DD);
        ((float4*)ys)[t] = yp[t];   // 256 * float4 = 1024
    }
    __syncthreads();

    const int tx = t & 15, ty = t >> 4;
    float acc[8][8];
#pragma unroll
    for (int i = 0; i < 8; i++)
#pragma unroll
        for (int j = 0; j < 8; j++) acc[i][j] = 0.0f;

    const float* xb_ = x + (size_t)b * NN * DD;
    const float* Wc_ = W + h0;

    for (int d0 = 0; d0 < DD; d0 += 16) {
        // As[k][n] = x[b][n][d0+k] * ys[d0+k]
#pragma unroll
        for (int i = 0; i < 2; i++) {
            int lin = t + i * 256;       // 0..511 (float4 units)
            int n   = lin >> 2;          // 0..127
            int c4  = (lin & 3) * 4;     // 0,4,8,12
            float4 xv = *(const float4*)(xb_ + (size_t)n * DD + d0 + c4);
            As[c4 + 0][n] = xv.x * ys[d0 + c4 + 0];
            As[c4 + 1][n] = xv.y * ys[d0 + c4 + 1];
            As[c4 + 2][n] = xv.z * ys[d0 + c4 + 2];
            As[c4 + 3][n] = xv.w * ys[d0 + c4 + 3];
        }
        // Bs[k][h] = W[d0+k][h0+h]
#pragma unroll
        for (int i = 0; i < 2; i++) {
            int lin = t + i * 256;       // 0..511
            int k   = lin >> 5;          // 0..15
            int h4  = (lin & 31) * 4;    // 0..124
            *(float4*)&Bs[k][h4] = *(const float4*)(Wc_ + (size_t)(d0 + k) * HH + h4);
        }
        __syncthreads();
#pragma unroll
        for (int k = 0; k < 16; k++) {
            float af[8], bf[8];
            *(float4*)&af[0] = *(const float4*)&As[k][ty * 8];
            *(float4*)&af[4] = *(const float4*)&As[k][ty * 8 + 4];
            *(float4*)&bf[0] = *(const float4*)&Bs[k][tx * 8];
            *(float4*)&bf[4] = *(const float4*)&Bs[k][tx * 8 + 4];
#pragma unroll
            for (int i = 0; i < 8; i++)
#pragma unroll
                for (int j = 0; j < 8; j++)
                    acc[i][j] = fmaf(af[i], bf[j], acc[i][j]);
        }
        __syncthreads();
    }

    // epilogue: tanh * v, partial row sums, reduce across tx
    float rowsum[8];
#pragma unroll
    for (int i = 0; i < 8; i++) rowsum[i] = 0.0f;
#pragma unroll
    for (int j = 0; j < 8; j++) {
        float vh = v[h0 + tx * 8 + j];
#pragma unroll
        for (int i = 0; i < 8; i++)
            rowsum[i] += ftanh(acc[i][j]) * vh;
    }
#pragma unroll
    for (int i = 0; i < 8; i++) red[ty][tx][i] = rowsum[i];
    __syncthreads();
    if (t < 128) {
        int n = t, tyy = n >> 3, ii = n & 7;
        float s = 0.0f;
#pragma unroll
        for (int xx = 0; xx < 16; xx++) s += red[tyy][xx][ii];
        spart[(((size_t)b * NN + m) * 4 + hc) * NN + n] = s;
    }
}

// ---------------------------------------------------------------------------
// Concat/minus scores: s[b,m,n] = sum_h v_h * tanh(p[b,n,h] + sign*q[b,m,h])
// grid (128 m, 8 b), 256 threads (8 warps, one n per warp per pass)
// ---------------------------------------------------------------------------
__global__ __launch_bounds__(256) void pair_scores(
    const float* __restrict__ p, const float* __restrict__ q,
    const float* __restrict__ v, float* __restrict__ s, float sign)
{
    const int m = blockIdx.x, b = blockIdx.y;
    const int t = threadIdx.x, lane = t & 31, w = t >> 5;
    __shared__ float qs[HH], vs[HH];
    if (t < 128) {
        ((float4*)qs)[t] = ((const float4*)(q + ((size_t)b * NN + m) * HH))[t];
        ((float4*)vs)[t] = ((const float4*)v)[t];
    }
    __syncthreads();
    const float* pb = p + (size_t)b * NN * HH;
    for (int n = w; n < NN; n += 8) {
        const float* pr = pb + (size_t)n * HH;
        float acc = 0.0f;
#pragma unroll
        for (int h = 0; h < HH; h += 32) {
            int hh = h + lane;
            acc += vs[hh] * ftanh(fmaf(sign, qs[hh], pr[hh]));
        }
#pragma unroll
        for (int o = 16; o; o >>= 1) acc += __shfl_xor_sync(0xffffffffu, acc, o);
        if (lane == 0) s[((size_t)b * NN + m) * NN + n] = acc;
    }
}

// ---------------------------------------------------------------------------
// Bilinear scores: s[b,m,n] = sum_d x1[b,m,d] * xb[b,n,d]
// ---------------------------------------------------------------------------
__global__ __launch_bounds__(256) void bilin_scores(
    const float* __restrict__ y, const float* __restrict__ xb,
    float* __restrict__ s)
{
    const int m = blockIdx.x, b = blockIdx.y;
    const int t = threadIdx.x, lane = t & 31, w = t >> 5;
    __shared__ float ysm[DD];
    ((float4*)ysm)[t] = ((const float4*)(y + ((size_t)b * NN + m) * DD))[t];
    __syncthreads();
    const float* xbb = xb + (size_t)b * NN * DD;
    for (int n = w; n < NN; n += 8) {
        const float* xr = xbb + (size_t)n * DD;
        float acc = 0.0f;
#pragma unroll 8
        for (int d = lane; d < DD; d += 32) acc += ysm[d] * xr[d];
#pragma unroll
        for (int o = 16; o; o >>= 1) acc += __shfl_xor_sync(0xffffffffu, acc, o);
        if (lane == 0) s[((size_t)b * NN + m) * NN + n] = acc;
    }
}

// ---------------------------------------------------------------------------
// w1v[j] = sum_h Wp1[j,h] * vp[h]    (2048 rows of 512)
// grid 256 blocks x 256 threads; one warp per row
// ---------------------------------------------------------------------------
__global__ void w1v_kernel(const float* __restrict__ Wp1,
                           const float* __restrict__ vp,
                           float* __restrict__ w1v)
{
    int j = blockIdx.x * 8 + (threadIdx.x >> 5);
    int lane = threadIdx.x & 31;
    const float* r = Wp1 + (size_t)j * HH;
    float acc = 0.0f;
#pragma unroll
    for (int h = lane; h < HH; h += 32) acc += r[h] * vp[h];
#pragma unroll
    for (int o = 16; o; o >>= 1) acc += __shfl_xor_sync(0xffffffffu, acc, o);
    if (lane == 0) w1v[j] = acc;
}

// ---------------------------------------------------------------------------
// Fused: 5 softmaxes + 5 weighted sums + elementwise max + agg_rep write.
// grid (128 m, 8 b), 256 threads. Each thread owns 4 consecutive d.
// ---------------------------------------------------------------------------
__global__ __launch_bounds__(256) void fuse_att(
    const float* __restrict__ sc,  const float* __restrict__ sb,
    const float* __restrict__ smn, const float* __restrict__ sd1,
    const float* __restrict__ sd2,
    const float* __restrict__ x0,  const float* __restrict__ x1,
    float* __restrict__ aggrep)
{
    const int m = blockIdx.x, b = blockIdx.y;
    const int t = threadIdx.x, lane = t & 31, w = t >> 5;
    const size_t bm = (size_t)b * NN + m;
    __shared__ float aw[5][NN];

    if (t < 128) {
        aw[0][t] = sc [bm * NN + t];
        aw[1][t] = sb [bm * NN + t];
        aw[2][t] = smn[bm * NN + t];
        float s1 = 0.0f, s2 = 0.0f;
#pragma unroll
        for (int hc = 0; hc < 4; hc++) {
            s1 += sd1[(bm * 4 + hc) * NN + t];
            s2 += sd2[(bm * 4 + hc) * NN + t];
        }
        aw[3][t] = s1; aw[4][t] = s2;
    }
    __syncthreads();

    if (w < 5) {  // warp w does softmax over 128 values of row w
        float v0 = aw[w][lane], v1 = aw[w][lane + 32];
        float v2 = aw[w][lane + 64], v3 = aw[w][lane + 96];
        float mx = fmaxf(fmaxf(v0, v1), fmaxf(v2, v3));
#pragma unroll
        for (int o = 16; o; o >>= 1) mx = fmaxf(mx, __shfl_xor_sync(0xffffffffu, mx, o));
        float e0 = __expf(v0 - mx), e1 = __expf(v1 - mx);
        float e2 = __expf(v2 - mx), e3 = __expf(v3 - mx);
        float sm = e0 + e1 + e2 + e3;
#pragma unroll
        for (int o = 16; o; o >>= 1) sm += __shfl_xor_sync(0xffffffffu, sm, o);
        float inv = 1.0f / sm;
        aw[w][lane]      = e0 * inv; aw[w][lane + 32] = e1 * inv;
        aw[w][lane + 64] = e2 * inv; aw[w][lane + 96] = e3 * inv;
    }
    __syncthreads();

    const int d = t * 4;
    float4 aC = {0,0,0,0}, aB = {0,0,0,0}, aS = {0,0,0,0}, aM = {0,0,0,0}, aD = {0,0,0,0};
    const float* x0b = x0 + (size_t)b * NN * DD;
    const float* x1b = x1 + (size_t)b * NN * DD;
    for (int n = 0; n < NN; n++) {
        float4 xv = *(const float4*)(x0b + (size_t)n * DD + d);
        float wc = aw[0][n], wb2 = aw[1][n], wm2 = aw[2][n], ws = aw[3][n];
        aC.x = fmaf(wc, xv.x, aC.x); aC.y = fmaf(wc, xv.y, aC.y);
        aC.z = fmaf(wc, xv.z, aC.z); aC.w = fmaf(wc, xv.w, aC.w);
        aB.x = fmaf(wb2, xv.x, aB.x); aB.y = fmaf(wb2, xv.y, aB.y);
        aB.z = fmaf(wb2, xv.z, aB.z); aB.w = fmaf(wb2, xv.w, aB.w);
        aM.x = fmaf(wm2, xv.x, aM.x); aM.y = fmaf(wm2, xv.y, aM.y);
        aM.z = fmaf(wm2, xv.z, aM.z); aM.w = fmaf(wm2, xv.w, aM.w);
        aS.x = fmaf(ws, xv.x, aS.x); aS.y = fmaf(ws, xv.y, aS.y);
        aS.z = fmaf(ws, xv.z, aS.z); aS.w = fmaf(ws, xv.w, aS.w);
        float4 yv = *(const float4*)(x1b + (size_t)n * DD + d);
        float wd = aw[4][n];
        aD.x = fmaf(wd, yv.x, aD.x); aD.y = fmaf(wd, yv.y, aD.y);
        aD.z = fmaf(wd, yv.z, aD.z); aD.w = fmaf(wd, yv.w, aD.w);
    }
    float4 xm1 = *(const float4*)(x1b + (size_t)m * DD + d);
    float4 ag;
    ag.x = fmaxf(xm1.x, fmaxf(fmaxf(aS.x, aC.x), fmaxf(fmaxf(aD.x, aB.x), aM.x)));
    ag.y = fmaxf(xm1.y, fmaxf(fmaxf(aS.y, aC.y), fmaxf(fmaxf(aD.y, aB.y), aM.y)));
    ag.z = fmaxf(xm1.z, fmaxf(fmaxf(aS.z, aC.z), fmaxf(fmaxf(aD.z, aB.z), aM.z)));
    ag.w = fmaxf(xm1.w, fmaxf(fmaxf(aS.w, aC.w), fmaxf(fmaxf(aD.w, aB.w), aM.w)));
    float* arow = aggrep + bm * (2 * DD);
    *(float4*)(arow + d)      = xm1;   // agg_rep[:, 0:1024]   = x1
    *(float4*)(arow + DD + d) = ag;    // agg_rep[:, 1024:2048] = max(...)
}

// ---------------------------------------------------------------------------
// Final: per b: score_m = agg_rep[b,m,:].w1v; sp = softmax_m; rp = sp.agg_rep;
//        out = relu(rp @ Wpred + bpred).   grid 8, 256 threads.
// ---------------------------------------------------------------------------
__global__ __launch_bounds__(256) void final_kernel(
    const float* __restrict__ aggrep, const float* __restrict__ w1v,
    const float* __restrict__ Wpred,  const float* __restrict__ bpred,
    float* __restrict__ out)
{
    const int b = blockIdx.x;
    const int t = threadIdx.x, lane = t & 31, w = t >> 5;
    __shared__ float sp[NN];
    __shared__ float r0[8], r1[8];
    const float* ab = aggrep + (size_t)b * NN * (2 * DD);

    for (int mm = w; mm < NN; mm += 8) {
        const float* ar = ab + (size_t)mm * (2 * DD);
        float acc = 0.0f;
#pragma unroll
        for (int j = lane; j < 2 * DD; j += 32) acc += ar[j] * w1v[j];
#pragma unroll
        for (int o = 16; o; o >>= 1) acc += __shfl_xor_sync(0xffffffffu, acc, o);
        if (lane == 0) sp[mm] = acc;
    }
    __syncthreads();
    if (w == 0) {
        float v0 = sp[lane], v1 = sp[lane + 32], v2 = sp[lane + 64], v3 = sp[lane + 96];
        float mx = fmaxf(fmaxf(v0, v1), fmaxf(v2, v3));
#pragma unroll
        for (int o = 16; o; o >>= 1) mx = fmaxf(mx, __shfl_xor_sync(0xffffffffu, mx, o));
        float e0 = __expf(v0 - mx), e1 = __expf(v1 - mx);
        float e2 = __expf(v2 - mx), e3 = __expf(v3 - mx);
        float sm = e0 + e1 + e2 + e3;
#pragma unroll
        for (int o = 16; o; o >>= 1) sm += __shfl_xor_sync(0xffffffffu, sm, o);
        float inv = 1.0f / sm;
        sp[lane] = e0 * inv; sp[lane + 32] = e1 * inv;
        sp[lane + 64] = e2 * inv; sp[lane + 96] = e3 * inv;
    }
    __syncthreads();

    float rp[8];
#pragma unroll
    for (int k = 0; k < 8; k++) rp[k] = 0.0f;
    for (int mm = 0; mm < NN; mm++) {
        float wgt = sp[mm];
        const float* ar = ab + (size_t)mm * (2 * DD);
#pragma unroll
        for (int k = 0; k < 8; k++) rp[k] = fmaf(wgt, ar[t + k * 256], rp[k]);
    }
    float p0 = 0.0f, p1 = 0.0f;
#pragma unroll
    for (int k = 0; k < 8; k++) {
        int j = t + k * 256;
        p0 = fmaf(rp[k], Wpred[(size_t)j * 2 + 0], p0);
        p1 = fmaf(rp[k], Wpred[(size_t)j * 2 + 1], p1);
    }
#pragma unroll
    for (int o = 16; o; o >>= 1) {
        p0 += __shfl_xor_sync(0xffffffffu, p0, o);
        p1 += __shfl_xor_sync(0xffffffffu, p1, o);
    }
    if (lane == 0) { r0[w] = p0; r1[w] = p1; }
    __syncthreads();
    if (t == 0) {
        float s0 = 0.0f, s1 = 0.0f;
#pragma unroll
        for (int i = 0; i < 8; i++) { s0 += r0[i]; s1 += r1[i]; }
        out[b * 2 + 0] = fmaxf(s0 + bpred[0], 0.0f);
        out[b * 2 + 1] = fmaxf(s1 + bpred[1], 0.0f);
    }
}

// ---------------------------------------------------------------------------
extern "C" void kernel_launch(void* const* d_in, const int* in_sizes, int n_in,
                              void* d_out, int out_size)
{
    (void)in_sizes; (void)n_in; (void)out_size;
    float* S = nullptr;
    cudaGetSymbolAddress((void**)&S, g_scratch);

    const float* x0    = (const float*)d_in[0];
    const float* x1    = (const float*)d_in[1];
    const float* Wc1   = (const float*)d_in[2];
    const float* Wc2   = (const float*)d_in[3];
    const float* vc    = (const float*)d_in[4];
    const float* Wb    = (const float*)d_in[5];
    const float* Wd1   = (const float*)d_in[6];
    const float* vd1   = (const float*)d_in[7];
    const float* Wd2   = (const float*)d_in[8];
    const float* vd2   = (const float*)d_in[9];
    const float* Wm    = (const float*)d_in[10];
    const float* vm    = (const float*)d_in[11];
    // d_in[12] Wq, d_in[13] vq, d_in[15] Wp2: provably cancel in the softmax
    const float* Wp1   = (const float*)d_in[14];
    const float* vp    = (const float*)d_in[16];
    const float* Wpred = (const float*)d_in[17];
    const float* bpred = (const float*)d_in[18];
    float* out = (float*)d_out;

    const int M = BB * NN;  // 1024

    // Projections
    gemm_nn<<<dim3(HH / 64, M / 64), 256>>>(x0, Wc1, S + OFF_XC, M, DD, HH);
    gemm_nn<<<dim3(HH / 64, M / 64), 256>>>(x1, Wc2, S + OFF_YC, M, DD, HH);
    gemm_nn<<<dim3(HH / 64, M / 64), 256>>>(x0, Wm,  S + OFF_XM, M, DD, HH);
    gemm_nn<<<dim3(HH / 64, M / 64), 256>>>(x1, Wm,  S + OFF_YM, M, DD, HH);
    gemm_nn<<<dim3(DD / 64, M / 64), 256>>>(x0, Wb,  S + OFF_XB, M, DD, DD);

    // Scores
    dot_scores<<<dim3(4, NN, BB), 256>>>(x0, x1, Wd1, vd1, S + OFF_SD1);
    dot_scores<<<dim3(4, NN, BB), 256>>>(x1, x0, Wd2, vd2, S + OFF_SD2);
    pair_scores<<<dim3(NN, BB), 256>>>(S + OFF_XC, S + OFF_YC, vc, S + OFF_SC,  1.0f);
    pair_scores<<<dim3(NN, BB), 256>>>(S + OFF_XM, S + OFF_YM, vm, S + OFF_SMN, -1.0f);
    bilin_scores<<<dim3(NN, BB), 256>>>(x1, S + OFF_XB, S + OFF_SB);

    // Aggregation precompute + fused attention + final
    w1v_kernel<<<256, 256>>>(Wp1, vp, S + OFF_W1V);
    fuse_att<<<dim3(NN, BB), 256>>>(S + OFF_SC, S + OFF_SB, S + OFF_SMN,
                                    S + OFF_SD1, S + OFF_SD2, x0, x1, S + OFF_AGG);
    final_kernel<<<BB, 256>>>(S + OFF_AGG, S + OFF_W1V, Wpred, bpred, out);
}

// round 2
// speedup vs baseline: 1.0005x; 1.0005x over previous
#include <cuda_runtime.h>
#include <cstddef>

// ---------------------------------------------------------------------------
// Problem constants: B=8, N=M=128, H=512, D=2H=1024
// ---------------------------------------------------------------------------
#define BB   8
#define NN   128
#define HH   512
#define DD   1024

// Scratch layout (floats)
#define SZ_PROJ (BB*NN*HH)      // 524288
#define SZ_XB   (BB*NN*DD)      // 1048576
#define SZ_S    (BB*NN*NN)      // 131072
#define SZ_SD   (BB*NN*4*NN)    // 524288
#define SZ_AGG  (BB*NN*2*DD)    // 2097152

#define OFF_XC  0
#define OFF_YC  (OFF_XC + SZ_PROJ)
#define OFF_XM  (OFF_YC + SZ_PROJ)
#define OFF_YM  (OFF_XM + SZ_PROJ)
#define OFF_XB  (OFF_YM + SZ_PROJ)
#define OFF_SC  (OFF_XB + SZ_XB)
#define OFF_SB  (OFF_SC + SZ_S)
#define OFF_SMN (OFF_SB + SZ_S)
#define OFF_SD1 (OFF_SMN + SZ_S)
#define OFF_SD2 (OFF_SD1 + SZ_SD)
#define OFF_AGG (OFF_SD2 + SZ_SD)
#define OFF_W1V (OFF_AGG + SZ_AGG)
#define SCRATCH_TOTAL (OFF_W1V + 2*DD)

__device__ float g_scratch[SCRATCH_TOTAL];

// tanh(x) = 1 - 2/(exp(2x)+1); abs error <= ~1e-7, saturates correctly at +-1.
__device__ __forceinline__ float ftanh(float x) {
    float e = __expf(2.0f * x);
    return 1.0f - __fdividef(2.0f, e + 1.0f);
}

// ---------------------------------------------------------------------------
// Generic fp32 GEMM: C[M,N] = A[M,K] @ W[K,N], all row-major.
// BM=BN=64, BK=16, 256 threads, 4x4 per thread. M,N multiples of 64, K of 16.
// ---------------------------------------------------------------------------
__global__ __launch_bounds__(256) void gemm_nn(
    const float* __restrict__ A, const float* __restrict__ W,
    float* __restrict__ C, int M, int K, int N)
{
    __shared__ float As[16][68];
    __shared__ float Bs[16][68];
    const int bm = blockIdx.y * 64, bn = blockIdx.x * 64;
    const int t = threadIdx.x;
    const int tx = t & 15, ty = t >> 4;

    float acc[4][4];
#pragma unroll
    for (int i = 0; i < 4; i++)
#pragma unroll
        for (int j = 0; j < 4; j++) acc[i][j] = 0.0f;

    for (int k0 = 0; k0 < K; k0 += 16) {
#pragma unroll
        for (int i = 0; i < 4; i++) {
            int idx = t + i * 256;           // 0..1023
            int r = idx >> 4, c = idx & 15;  // A: 64 rows x 16 cols
            As[c][r] = A[(size_t)(bm + r) * K + k0 + c];
        }
#pragma unroll
        for (int i = 0; i < 4; i++) {
            int idx = t + i * 256;
            int r = idx >> 6, c = idx & 63;  // W: 16 rows x 64 cols
            Bs[r][c] = W[(size_t)(k0 + r) * N + bn + c];
        }
        __syncthreads();
#pragma unroll
        for (int k = 0; k < 16; k++) {
            float a[4], bv[4];
#pragma unroll
            for (int i = 0; i < 4; i++) a[i] = As[k][ty * 4 + i];
#pragma unroll
            for (int j = 0; j < 4; j++) bv[j] = Bs[k][tx * 4 + j];
#pragma unroll
            for (int i = 0; i < 4; i++)
#pragma unroll
                for (int j = 0; j < 4; j++)
                    acc[i][j] = fmaf(a[i], bv[j], acc[i][j]);
        }
        __syncthreads();
    }
#pragma unroll
    for (int i = 0; i < 4; i++)
#pragma unroll
        for (int j = 0; j < 4; j++)
            C[(size_t)(bm + ty * 4 + i) * N + bn + tx * 4 + j] = acc[i][j];
}

// ---------------------------------------------------------------------------
// Fused dot-attention scores (the dominant ~137 GF each):
//   spart[b][m][hc][n] = sum_{h in chunk hc} v_h * tanh( sum_d x[b,n,d]*y[b,m,d]*W[d,h] )
// grid (4 h-chunks, 128 m, 8 b), 256 threads, 128x128 tile, 8x8 per thread.
// ---------------------------------------------------------------------------
__global__ __launch_bounds__(256) void dot_scores(
    const float* __restrict__ x, const float* __restrict__ y,
    const float* __restrict__ W, const float* __restrict__ v,
    float* __restrict__ spart)
{
    const int hc = blockIdx.x;
    const int m  = blockIdx.y;
    const int b  = blockIdx.z;
    const int h0 = hc * 128;
    const int t  = threadIdx.x;

    __shared__ __align__(16) float ys[DD];
    __shared__ __align__(16) float As[16][132];
    __shared__ __align__(16) float Bs[16][132];
    __shared__ float red[16][16][8];

    {   // y[b][m][:] -> smem
        const float4* yp = (const float4*)(y + ((size_t)b * NN + m) * DD);
        ((float4*)ys)[t] = yp[t];   // 256 * float4 = 1024
    }
    __syncthreads();

    const int tx = t & 15, ty = t >> 4;
    float acc[8][8];
#pragma unroll
    for (int i = 0; i < 8; i++)
#pragma unroll
        for (int j = 0; j < 8; j++) acc[i][j] = 0.0f;

    const float* xb_ = x + (size_t)b * NN * DD;
    const float* Wc_ = W + h0;

    for (int d0 = 0; d0 < DD; d0 += 16) {
        // As[k][n] = x[b][n][d0+k] * ys[d0+k]
#pragma unroll
        for (int i = 0; i < 2; i++) {
            int lin = t + i * 256;       // 0..511 (float4 units)
            int n   = lin >> 2;          // 0..127
            int c4  = (lin & 3) * 4;     // 0,4,8,12
            float4 xv = *(const float4*)(xb_ + (size_t)n * DD + d0 + c4);
            As[c4 + 0][n] = xv.x * ys[d0 + c4 + 0];
            As[c4 + 1][n] = xv.y * ys[d0 + c4 + 1];
            As[c4 + 2][n] = xv.z * ys[d0 + c4 + 2];
            As[c4 + 3][n] = xv.w * ys[d0 + c4 + 3];
        }
        // Bs[k][h] = W[d0+k][h0+h]
#pragma unroll
        for (int i = 0; i < 2; i++) {
            int lin = t + i * 256;       // 0..511
            int k   = lin >> 5;          // 0..15
            int h4  = (lin & 31) * 4;    // 0..124
            *(float4*)&Bs[k][h4] = *(const float4*)(Wc_ + (size_t)(d0 + k) * HH + h4);
        }
        __syncthreads();
#pragma unroll
        for (int k = 0; k < 16; k++) {
            float af[8], bf[8];
            *(float4*)&af[0] = *(const float4*)&As[k][ty * 8];
            *(float4*)&af[4] = *(const float4*)&As[k][ty * 8 + 4];
            *(float4*)&bf[0] = *(const float4*)&Bs[k][tx * 8];
            *(float4*)&bf[4] = *(const float4*)&Bs[k][tx * 8 + 4];
#pragma unroll
            for (int i = 0; i < 8; i++)
#pragma unroll
                for (int j = 0; j < 8; j++)
                    acc[i][j] = fmaf(af[i], bf[j], acc[i][j]);
        }
        __syncthreads();
    }

    // epilogue: tanh * v, partial row sums, reduce across tx
    float rowsum[8];
#pragma unroll
    for (int i = 0; i < 8; i++) rowsum[i] = 0.0f;
#pragma unroll
    for (int j = 0; j < 8; j++) {
        float vh = v[h0 + tx * 8 + j];
#pragma unroll
        for (int i = 0; i < 8; i++)
            rowsum[i] += ftanh(acc[i][j]) * vh;
    }
#pragma unroll
    for (int i = 0; i < 8; i++) red[ty][tx][i] = rowsum[i];
    __syncthreads();
    if (t < 128) {
        int n = t, tyy = n >> 3, ii = n & 7;
        float s = 0.0f;
#pragma unroll
        for (int xx = 0; xx < 16; xx++) s += red[tyy][xx][ii];
        spart[(((size_t)b * NN + m) * 4 + hc) * NN + n] = s;
    }
}

// ---------------------------------------------------------------------------
// Concat/minus scores: s[b,m,n] = sum_h v_h * tanh(p[b,n,h] + sign*q[b,m,h])
// grid (128 m, 8 b), 256 threads (8 warps, one n per warp per pass)
// ---------------------------------------------------------------------------
__global__ __launch_bounds__(256) void pair_scores(
    const float* __restrict__ p, const float* __restrict__ q,
    const float* __restrict__ v, float* __restrict__ s, float sign)
{
    const int m = blockIdx.x, b = blockIdx.y;
    const int t = threadIdx.x, lane = t & 31, w = t >> 5;
    __shared__ float qs[HH], vs[HH];
    if (t < 128) {
        ((float4*)qs)[t] = ((const float4*)(q + ((size_t)b * NN + m) * HH))[t];
        ((float4*)vs)[t] = ((const float4*)v)[t];
    }
    __syncthreads();
    const float* pb = p + (size_t)b * NN * HH;
    for (int n = w; n < NN; n += 8) {
        const float* pr = pb + (size_t)n * HH;
        float acc = 0.0f;
#pragma unroll
        for (int h = 0; h < HH; h += 32) {
            int hh = h + lane;
            acc += vs[hh] * ftanh(fmaf(sign, qs[hh], pr[hh]));
        }
#pragma unroll
        for (int o = 16; o; o >>= 1) acc += __shfl_xor_sync(0xffffffffu, acc, o);
        if (lane == 0) s[((size_t)b * NN + m) * NN + n] = acc;
    }
}

// ---------------------------------------------------------------------------
// Bilinear scores: s[b,m,n] = sum_d x1[b,m,d] * xb[b,n,d]
// ---------------------------------------------------------------------------
__global__ __launch_bounds__(256) void bilin_scores(
    const float* __restrict__ y, const float* __restrict__ xb,
    float* __restrict__ s)
{
    const int m = blockIdx.x, b = blockIdx.y;
    const int t = threadIdx.x, lane = t & 31, w = t >> 5;
    __shared__ float ysm[DD];
    ((float4*)ysm)[t] = ((const float4*)(y + ((size_t)b * NN + m) * DD))[t];
    __syncthreads();
    const float* xbb = xb + (size_t)b * NN * DD;
    for (int n = w; n < NN; n += 8) {
        const float* xr = xbb + (size_t)n * DD;
        float acc = 0.0f;
#pragma unroll 8
        for (int d = lane; d < DD; d += 32) acc += ysm[d] * xr[d];
#pragma unroll
        for (int o = 16; o; o >>= 1) acc += __shfl_xor_sync(0xffffffffu, acc, o);
        if (lane == 0) s[((size_t)b * NN + m) * NN + n] = acc;
    }
}

// ---------------------------------------------------------------------------
// w1v[j] = sum_h Wp1[j,h] * vp[h]    (2048 rows of 512)
// grid 256 blocks x 256 threads; one warp per row
// ---------------------------------------------------------------------------
__global__ void w1v_kernel(const float* __restrict__ Wp1,
                           const float* __restrict__ vp,
                           float* __restrict__ w1v)
{
    int j = blockIdx.x * 8 + (threadIdx.x >> 5);
    int lane = threadIdx.x & 31;
    const float* r = Wp1 + (size_t)j * HH;
    float acc = 0.0f;
#pragma unroll
    for (int h = lane; h < HH; h += 32) acc += r[h] * vp[h];
#pragma unroll
    for (int o = 16; o; o >>= 1) acc += __shfl_xor_sync(0xffffffffu, acc, o);
    if (lane == 0) w1v[j] = acc;
}

// ---------------------------------------------------------------------------
// Fused: 5 softmaxes + 5 weighted sums + elementwise max + agg_rep write.
// grid (128 m, 8 b), 256 threads. Each thread owns 4 consecutive d.
// ---------------------------------------------------------------------------
__global__ __launch_bounds__(256) void fuse_att(
    const float* __restrict__ sc,  const float* __restrict__ sb,
    const float* __restrict__ smn, const float* __restrict__ sd1,
    const float* __restrict__ sd2,
    const float* __restrict__ x0,  const float* __restrict__ x1,
    float* __restrict__ aggrep)
{
    const int m = blockIdx.x, b = blockIdx.y;
    const int t = threadIdx.x, lane = t & 31, w = t >> 5;
    const size_t bm = (size_t)b * NN + m;
    __shared__ float aw[5][NN];

    if (t < 128) {
        aw[0][t] = sc [bm * NN + t];
        aw[1][t] = sb [bm * NN + t];
        aw[2][t] = smn[bm * NN + t];
        float s1 = 0.0f, s2 = 0.0f;
#pragma unroll
        for (int hc = 0; hc < 4; hc++) {
            s1 += sd1[(bm * 4 + hc) * NN + t];
            s2 += sd2[(bm * 4 + hc) * NN + t];
        }
        aw[3][t] = s1; aw[4][t] = s2;
    }
    __syncthreads();

    if (w < 5) {  // warp w does softmax over 128 values of row w
        float v0 = aw[w][lane], v1 = aw[w][lane + 32];
        float v2 = aw[w][lane + 64], v3 = aw[w][lane + 96];
        float mx = fmaxf(fmaxf(v0, v1), fmaxf(v2, v3));
#pragma unroll
        for (int o = 16; o; o >>= 1) mx = fmaxf(mx, __shfl_xor_sync(0xffffffffu, mx, o));
        float e0 = __expf(v0 - mx), e1 = __expf(v1 - mx);
        float e2 = __expf(v2 - mx), e3 = __expf(v3 - mx);
        float sm = e0 + e1 + e2 + e3;
#pragma unroll
        for (int o = 16; o; o >>= 1) sm += __shfl_xor_sync(0xffffffffu, sm, o);
        float inv = 1.0f / sm;
        aw[w][lane]      = e0 * inv; aw[w][lane + 32] = e1 * inv;
        aw[w][lane + 64] = e2 * inv; aw[w][lane + 96] = e3 * inv;
    }
    __syncthreads();

    const int d = t * 4;
    float4 aC = {0,0,0,0}, aB = {0,0,0,0}, aS = {0,0,0,0}, aM = {0,0,0,0}, aD = {0,0,0,0};
    const float* x0b = x0 + (size_t)b * NN * DD;
    const float* x1b = x1 + (size_t)b * NN * DD;
    for (int n = 0; n < NN; n++) {
        float4 xv = *(const float4*)(x0b + (size_t)n * DD + d);
        float wc = aw[0][n], wb2 = aw[1][n], wm2 = aw[2][n], ws = aw[3][n];
        aC.x = fmaf(wc, xv.x, aC.x); aC.y = fmaf(wc, xv.y, aC.y);
        aC.z = fmaf(wc, xv.z, aC.z); aC.w = fmaf(wc, xv.w, aC.w);
        aB.x = fmaf(wb2, xv.x, aB.x); aB.y = fmaf(wb2, xv.y, aB.y);
        aB.z = fmaf(wb2, xv.z, aB.z); aB.w = fmaf(wb2, xv.w, aB.w);
        aM.x = fmaf(wm2, xv.x, aM.x); aM.y = fmaf(wm2, xv.y, aM.y);
        aM.z = fmaf(wm2, xv.z, aM.z); aM.w = fmaf(wm2, xv.w, aM.w);
        aS.x = fmaf(ws, xv.x, aS.x); aS.y = fmaf(ws, xv.y, aS.y);
        aS.z = fmaf(ws, xv.z, aS.z); aS.w = fmaf(ws, xv.w, aS.w);
        float4 yv = *(const float4*)(x1b + (size_t)n * DD + d);
        float wd = aw[4][n];
        aD.x = fmaf(wd, yv.x, aD.x); aD.y = fmaf(wd, yv.y, aD.y);
        aD.z = fmaf(wd, yv.z, aD.z); aD.w = fmaf(wd, yv.w, aD.w);
    }
    float4 xm1 = *(const float4*)(x1b + (size_t)m * DD + d);
    float4 ag;
    ag.x = fmaxf(xm1.x, fmaxf(fmaxf(aS.x, aC.x), fmaxf(fmaxf(aD.x, aB.x), aM.x)));
    ag.y = fmaxf(xm1.y, fmaxf(fmaxf(aS.y, aC.y), fmaxf(fmaxf(aD.y, aB.y), aM.y)));
    ag.z = fmaxf(xm1.z, fmaxf(fmaxf(aS.z, aC.z), fmaxf(fmaxf(aD.z, aB.z), aM.z)));
    ag.w = fmaxf(xm1.w, fmaxf(fmaxf(aS.w, aC.w), fmaxf(fmaxf(aD.w, aB.w), aM.w)));
    float* arow = aggrep + bm * (2 * DD);
    *(float4*)(arow + d)      = xm1;   // agg_rep[:, 0:1024]   = x1
    *(float4*)(arow + DD + d) = ag;    // agg_rep[:, 1024:2048] = max(...)
}

// ---------------------------------------------------------------------------
// Final: per b: score_m = agg_rep[b,m,:].w1v; sp = softmax_m; rp = sp.agg_rep;
//        out = relu(rp @ Wpred + bpred).   grid 8, 256 threads.
// ---------------------------------------------------------------------------
__global__ __launch_bounds__(256) void final_kernel(
    const float* __restrict__ aggrep, const float* __restrict__ w1v,
    const float* __restrict__ Wpred,  const float* __restrict__ bpred,
    float* __restrict__ out)
{
    const int b = blockIdx.x;
    const int t = threadIdx.x, lane = t & 31, w = t >> 5;
    __shared__ float sp[NN];
    __shared__ float r0[8], r1[8];
    const float* ab = aggrep + (size_t)b * NN * (2 * DD);

    for (int mm = w; mm < NN; mm += 8) {
        const float* ar = ab + (size_t)mm * (2 * DD);
        float acc = 0.0f;
#pragma unroll
        for (int j = lane; j < 2 * DD; j += 32) acc += ar[j] * w1v[j];
#pragma unroll
        for (int o = 16; o; o >>= 1) acc += __shfl_xor_sync(0xffffffffu, acc, o);
        if (lane == 0) sp[mm] = acc;
    }
    __syncthreads();
    if (w == 0) {
        float v0 = sp[lane], v1 = sp[lane + 32], v2 = sp[lane + 64], v3 = sp[lane + 96];
        float mx = fmaxf(fmaxf(v0, v1), fmaxf(v2, v3));
#pragma unroll
        for (int o = 16; o; o >>= 1) mx = fmaxf(mx, __shfl_xor_sync(0xffffffffu, mx, o));
        float e0 = __expf(v0 - mx), e1 = __expf(v1 - mx);
        float e2 = __expf(v2 - mx), e3 = __expf(v3 - mx);
        float sm = e0 + e1 + e2 + e3;
#pragma unroll
        for (int o = 16; o; o >>= 1) sm += __shfl_xor_sync(0xffffffffu, sm, o);
        float inv = 1.0f / sm;
        sp[lane] = e0 * inv; sp[lane + 32] = e1 * inv;
        sp[lane + 64] = e2 * inv; sp[lane + 96] = e3 * inv;
    }
    __syncthreads();

    float rp[8];
#pragma unroll
    for (int k = 0; k < 8; k++) rp[k] = 0.0f;
    for (int mm = 0; mm < NN; mm++) {
        float wgt = sp[mm];
        const float* ar = ab + (size_t)mm * (2 * DD);
#pragma unroll
        for (int k = 0; k < 8; k++) rp[k] = fmaf(wgt, ar[t + k * 256], rp[k]);
    }
    float p0 = 0.0f, p1 = 0.0f;
#pragma unroll
    for (int k = 0; k < 8; k++) {
        int j = t + k * 256;
        p0 = fmaf(rp[k], Wpred[(size_t)j * 2 + 0], p0);
        p1 = fmaf(rp[k], Wpred[(size_t)j * 2 + 1], p1);
    }
#pragma unroll
    for (int o = 16; o; o >>= 1) {
        p0 += __shfl_xor_sync(0xffffffffu, p0, o);
        p1 += __shfl_xor_sync(0xffffffffu, p1, o);
    }
    if (lane == 0) { r0[w] = p0; r1[w] = p1; }
    __syncthreads();
    if (t == 0) {
        float s0 = 0.0f, s1 = 0.0f;
#pragma unroll
        for (int i = 0; i < 8; i++) { s0 += r0[i]; s1 += r1[i]; }
        out[b * 2 + 0] = fmaxf(s0 + bpred[0], 0.0f);
        out[b * 2 + 1] = fmaxf(s1 + bpred[1], 0.0f);
    }
}

// ---------------------------------------------------------------------------
extern "C" void kernel_launch(void* const* d_in, const int* in_sizes, int n_in,
                              void* d_out, int out_size)
{
    (void)in_sizes; (void)n_in; (void)out_size;
    float* S = nullptr;
    cudaGetSymbolAddress((void**)&S, g_scratch);

    const float* x0    = (const float*)d_in[0];
    const float* x1    = (const float*)d_in[1];
    const float* Wc1   = (const float*)d_in[2];
    const float* Wc2   = (const float*)d_in[3];
    const float* vc    = (const float*)d_in[4];
    const float* Wb    = (const float*)d_in[5];
    const float* Wd1   = (const float*)d_in[6];
    const float* vd1   = (const float*)d_in[7];
    const float* Wd2   = (const float*)d_in[8];
    const float* vd2   = (const float*)d_in[9];
    const float* Wm    = (const float*)d_in[10];
    const float* vm    = (const float*)d_in[11];
    // d_in[12] Wq, d_in[13] vq, d_in[15] Wp2: provably cancel in the softmax
    const float* Wp1   = (const float*)d_in[14];
    const float* vp    = (const float*)d_in[16];
    const float* Wpred = (const float*)d_in[17];
    const float* bpred = (const float*)d_in[18];
    float* out = (float*)d_out;

    const int M = BB * NN;  // 1024

    // Projections
    gemm_nn<<<dim3(HH / 64, M / 64), 256>>>(x0, Wc1, S + OFF_XC, M, DD, HH);
    gemm_nn<<<dim3(HH / 64, M / 64), 256>>>(x1, Wc2, S + OFF_YC, M, DD, HH);
    gemm_nn<<<dim3(HH / 64, M / 64), 256>>>(x0, Wm,  S + OFF_XM, M, DD, HH);
    gemm_nn<<<dim3(HH / 64, M / 64), 256>>>(x1, Wm,  S + OFF_YM, M, DD, HH);
    gemm_nn<<<dim3(DD / 64, M / 64), 256>>>(x0, Wb,  S + OFF_XB, M, DD, DD);

    // Scores
    dot_scores<<<dim3(4, NN, BB), 256>>>(x0, x1, Wd1, vd1, S + OFF_SD1);
    dot_scores<<<dim3(4, NN, BB), 256>>>(x1, x0, Wd2, vd2, S + OFF_SD2);
    pair_scores<<<dim3(NN, BB), 256>>>(S + OFF_XC, S + OFF_YC, vc, S + OFF_SC,  1.0f);
    pair_scores<<<dim3(NN, BB), 256>>>(S + OFF_XM, S + OFF_YM, vm, S + OFF_SMN, -1.0f);
    bilin_scores<<<dim3(NN, BB), 256>>>(x1, S + OFF_XB, S + OFF_SB);

    // Aggregation precompute + fused attention + final
    w1v_kernel<<<256, 256>>>(Wp1, vp, S + OFF_W1V);
    fuse_att<<<dim3(NN, BB), 256>>>(S + OFF_SC, S + OFF_SB, S + OFF_SMN,
                                    S + OFF_SD1, S + OFF_SD2, x0, x1, S + OFF_AGG);
    final_kernel<<<BB, 256>>>(S + OFF_AGG, S + OFF_W1V, Wpred, bpred, out);
}

// round 4
// speedup vs baseline: 2.2471x; 2.2460x over previous
#include <cuda_runtime.h>
#include <cuda_bf16.h>
#include <cstdint>
#include <cstddef>

// ---------------------------------------------------------------------------
// Problem constants: B=8, N=M=128, H=512, D=2H=1024
// ---------------------------------------------------------------------------
#define BB   8
#define NN   128
#define HH   512
#define DD   1024

// Scratch layout (floats)
#define SZ_PROJ (BB*NN*HH)
#define SZ_XB   (BB*NN*DD)
#define SZ_S    (BB*NN*NN)
#define SZ_SD   (BB*NN*2*NN)
#define SZ_AGG  (BB*NN*2*DD)

#define OFF_XC  0
#define OFF_YC  (OFF_XC + SZ_PROJ)
#define OFF_XM  (OFF_YC + SZ_PROJ)
#define OFF_YM  (OFF_XM + SZ_PROJ)
#define OFF_XB  (OFF_YM + SZ_PROJ)
#define OFF_SC  (OFF_XB + SZ_XB)
#define OFF_SB  (OFF_SC + SZ_S)
#define OFF_SMN (OFF_SB + SZ_S)
#define OFF_SD1 (OFF_SMN + SZ_S)
#define OFF_SD2 (OFF_SD1 + SZ_SD)
#define OFF_AGG (OFF_SD2 + SZ_SD)
#define OFF_W1V (OFF_AGG + SZ_AGG)
#define SCRATCH_TOTAL (OFF_W1V + 2*DD)

__device__ float g_scratch[SCRATCH_TOTAL];
// bf16 hi/lo split of W^T for the two dot attentions: [4][512*1024]
__device__ __nv_bfloat16 g_wt[4 * HH * DD];

// tanh(x) = 1 - 2/(exp(2x)+1)
__device__ __forceinline__ float ftanh(float x) {
    float e = __expf(2.0f * x);
    return 1.0f - __fdividef(2.0f, e + 1.0f);
}

__device__ __forceinline__ uint32_t smem_u32(const void* p) {
    uint32_t a;
    asm("{ .reg .u64 t; cvta.to.shared.u64 t, %1; cvt.u32.u64 %0, t; }" : "=r"(a) : "l"(p));
    return a;
}

#define LDSM4(r0, r1, r2, r3, addr) \
    asm volatile("ldmatrix.sync.aligned.m8n8.x4.shared.b16 {%0,%1,%2,%3}, [%4];" \
        : "=r"(r0), "=r"(r1), "=r"(r2), "=r"(r3) : "r"(addr))

#define MMA16816(d, a0, a1, a2, a3, b0, b1) \
    asm volatile("mma.sync.aligned.m16n8k16.row.col.f32.bf16.bf16.f32 " \
        "{%0,%1,%2,%3}, {%4,%5,%6,%7}, {%8,%9}, {%0,%1,%2,%3};" \
        : "+f"((d)[0]), "+f"((d)[1]), "+f"((d)[2]), "+f"((d)[3]) \
        : "r"(a0), "r"(a1), "r"(a2), "r"(a3), "r"(b0), "r"(b1))

#define CP_ASYNC16(sa, ga) \
    asm volatile("cp.async.cg.shared.global [%0], [%1], 16;" :: "r"(sa), "l"(ga))
#define CP_COMMIT() asm volatile("cp.async.commit_group;")
#define CP_WAIT0()  asm volatile("cp.async.wait_group 0;")

// 64B-row swizzle: byte ^ ((byte>>3)&0x30)  ==  chunk bits[5:4] ^= row bits[2:1]
__device__ __forceinline__ uint32_t sw64(uint32_t row, uint32_t chunk) {
    return row * 64u + ((chunk * 16u) ^ ((row & 6u) << 3));
}

// ---------------------------------------------------------------------------
// W^T bf16 hi/lo split:  wh/wl[h*1024 + d] = split(W[d*512 + h])
// ---------------------------------------------------------------------------
__global__ void wsplit_kernel(const float* __restrict__ W,
                              __nv_bfloat16* __restrict__ wh,
                              __nv_bfloat16* __restrict__ wl)
{
    int h = blockIdx.x;
#pragma unroll
    for (int i = 0; i < 4; i++) {
        int d = threadIdx.x + i * 256;
        float val = W[(size_t)d * HH + h];
        __nv_bfloat16 hb = __float2bfloat16(val);
        wh[(size_t)h * DD + d] = hb;
        wl[(size_t)h * DD + d] = __float2bfloat16(val - __bfloat162float(hb));
    }
}

// ---------------------------------------------------------------------------
// mma.sync bf16 3-split dot-attention scores.
// CTA per (hc in 0..1, m in 0..127, z = b*2+att). 512 threads, 16 warps.
// CTA tile: 128(n) x 256(h), K=1024 in kc=32 chunks, double-buffered.
//   z[n,h] = sum_d (x[n,d]*y[m,d]) * W[d,h]   (A split hi/lo, W pre-split)
//   spart[bm][hc][n] = sum_{h in chunk} v_h * tanh(z[n,h])
// ---------------------------------------------------------------------------
// Dynamic SMEM layout (bytes)
#define MOFF_Y  0            // 4096  (y row, 1024 f32)
#define MOFF_V  4096         // 1024  (v chunk, 256 f32)
#define MOFF_S  5120         // 512   (s reduction, 128 f32)
#define MOFF_A  8192         // A[buf][hi/lo]: 4 x 8192  -> ends 40960
#define MOFF_B  40960        // B[buf][hi/lo]: 4 x 16384 -> ends 106496
#define MSMEM   106496

__global__ __launch_bounds__(512, 1) void dot_scores_mma(
    const float* __restrict__ x0, const float* __restrict__ x1,
    const __nv_bfloat16* __restrict__ w1h, const __nv_bfloat16* __restrict__ w1l,
    const __nv_bfloat16* __restrict__ w2h, const __nv_bfloat16* __restrict__ w2l,
    const float* __restrict__ vd1, const float* __restrict__ vd2,
    float* __restrict__ sp1, float* __restrict__ sp2)
{
    extern __shared__ char smc[];
    const uint32_t sb = smem_u32(smc);

    const int hc  = blockIdx.x;           // 0..1   (h chunk of 256)
    const int m   = blockIdx.y;           // 0..127
    const int att = blockIdx.z & 1;
    const int b   = blockIdx.z >> 1;

    const float* x = att ? x1 : x0;
    const float* y = att ? x0 : x1;
    const __nv_bfloat16* wh = att ? w2h : w1h;
    const __nv_bfloat16* wl = att ? w2l : w1l;
    const float* v = att ? vd2 : vd1;
    float* spart = att ? sp2 : sp1;

    const int t = threadIdx.x;
    const int lane = t & 31, wid = t >> 5;
    const int wn = wid & 3, whi = wid >> 2;       // warp n-group, h-group
    const int lane15 = lane & 15, lhalf = lane >> 4;

    float* ysm = (float*)(smc + MOFF_Y);
    float* vsm = (float*)(smc + MOFF_V);
    float* ssm = (float*)(smc + MOFF_S);

    // preload y row, v chunk, zero s
    ((float2*)ysm)[t] = ((const float2*)(y + ((size_t)b * NN + m) * DD))[t];
    if (t < 64) ((float4*)vsm)[t] = ((const float4*)(v + hc * 256))[t];
    if (t < 128) ssm[t] = 0.0f;

    const float* xg = x + (size_t)b * NN * DD;
    const __nv_bfloat16* whg = wh + (size_t)(hc * 256) * DD;
    const __nv_bfloat16* wlg = wl + (size_t)(hc * 256) * DD;

    // per-thread tile coords
    const int an = t >> 2;                 // A row (n), 0..127
    const int ac = t & 3;                  // A 16B-chunk
    const uint32_t a_st = sw64(an, ac);    // A store offset
    const int br = t >> 2;                 // B row (first half), 0..127
    const int bc = t & 3;
    const uint32_t b_st0 = sw64(br, bc);
    const uint32_t b_st1 = b_st0 + 128 * 64;   // rows +128, same swizzle xor

    float xa0, xa1, xa2, xa3, xb0, xb1, xb2, xb3;   // staged x (8 floats)

    // ---- helpers (macros over locals) ----
#define ISSUE_B(kt, buf) do { \
        int k0_ = (kt) * 32; \
        const __nv_bfloat16* bp_ = whg + (size_t)br * DD + k0_ + bc * 8; \
        const __nv_bfloat16* lp_ = wlg + (size_t)br * DD + k0_ + bc * 8; \
        uint32_t Bh_ = sb + MOFF_B + (buf) * 32768u; \
        uint32_t Bl_ = Bh_ + 16384u; \
        CP_ASYNC16(Bh_ + b_st0, bp_); \
        CP_ASYNC16(Bh_ + b_st1, bp_ + 128 * DD); \
        CP_ASYNC16(Bl_ + b_st0, lp_); \
        CP_ASYNC16(Bl_ + b_st1, lp_ + 128 * DD); \
        CP_COMMIT(); \
    } while (0)

#define LOAD_X(kt) do { \
        int k0_ = (kt) * 32; \
        const float* xp_ = xg + (size_t)an * DD + k0_ + ac * 8; \
        float4 u_ = *(const float4*)xp_; \
        float4 w_ = *(const float4*)(xp_ + 4); \
        xa0 = u_.x; xa1 = u_.y; xa2 = u_.z; xa3 = u_.w; \
        xb0 = w_.x; xb1 = w_.y; xb2 = w_.z; xb3 = w_.w; \
    } while (0)

#define STORE_A(kt, buf) do { \
        int kb_ = (kt) * 32 + ac * 8; \
        float p_[8]; \
        p_[0] = xa0 * ysm[kb_ + 0]; p_[1] = xa1 * ysm[kb_ + 1]; \
        p_[2] = xa2 * ysm[kb_ + 2]; p_[3] = xa3 * ysm[kb_ + 3]; \
        p_[4] = xb0 * ysm[kb_ + 4]; p_[5] = xb1 * ysm[kb_ + 5]; \
        p_[6] = xb2 * ysm[kb_ + 6]; p_[7] = xb3 * ysm[kb_ + 7]; \
        union { __nv_bfloat16 h[8]; uint4 q; } uh_, ul_; \
        _Pragma("unroll") \
        for (int j_ = 0; j_ < 8; j_++) { \
            __nv_bfloat16 hb_ = __float2bfloat16(p_[j_]); \
            uh_.h[j_] = hb_; \
            ul_.h[j_] = __float2bfloat16(p_[j_] - __bfloat162float(hb_)); \
        } \
        char* Ab_ = smc + MOFF_A + (buf) * 16384; \
        *(uint4*)(Ab_ + a_st) = uh_.q; \
        *(uint4*)(Ab_ + 8192 + a_st) = ul_.q; \
    } while (0)

    float acc[2][8][4];
#pragma unroll
    for (int i = 0; i < 2; i++)
#pragma unroll
        for (int j = 0; j < 8; j++)
#pragma unroll
            for (int k = 0; k < 4; k++) acc[i][j][k] = 0.0f;

    // prologue: fill buffer 0
    ISSUE_B(0, 0);
    LOAD_X(0);
    __syncthreads();            // ysm ready before STORE_A uses it
    STORE_A(0, 0);
    CP_WAIT0();
    __syncthreads();

    // precomputed ldmatrix row offsets
    uint32_t a_row[2], b_row[4];
#pragma unroll
    for (int mi = 0; mi < 2; mi++) a_row[mi] = wn * 32 + mi * 16 + lane15;
#pragma unroll
    for (int nj = 0; nj < 4; nj++) b_row[nj] = whi * 64 + nj * 16 + lane15;

    for (int kt = 0; kt < 32; kt++) {
        const int buf = kt & 1;
        if (kt < 31) { ISSUE_B(kt + 1, buf ^ 1); LOAD_X(kt + 1); }

        const uint32_t Ah = sb + MOFF_A + buf * 16384u;
        const uint32_t Al = Ah + 8192u;
        const uint32_t Bh = sb + MOFF_B + buf * 32768u;
        const uint32_t Bl = Bh + 16384u;

#pragma unroll
        for (int ks = 0; ks < 2; ks++) {
            const uint32_t cidx = ks * 2 + lhalf;
            uint32_t a[2][4], bb[4][4];
            // A_hi fragments
#pragma unroll
            for (int mi = 0; mi < 2; mi++)
                LDSM4(a[mi][0], a[mi][1], a[mi][2], a[mi][3], Ah + sw64(a_row[mi], cidx));
            // B_hi fragments
#pragma unroll
            for (int nj = 0; nj < 4; nj++)
                LDSM4(bb[nj][0], bb[nj][1], bb[nj][2], bb[nj][3], Bh + sw64(b_row[nj], cidx));
            // a_hi * b_hi
#pragma unroll
            for (int mi = 0; mi < 2; mi++)
#pragma unroll
                for (int nj = 0; nj < 4; nj++) {
                    MMA16816(acc[mi][nj*2+0], a[mi][0], a[mi][1], a[mi][2], a[mi][3], bb[nj][0], bb[nj][2]);
                    MMA16816(acc[mi][nj*2+1], a[mi][0], a[mi][1], a[mi][2], a[mi][3], bb[nj][1], bb[nj][3]);
                }
            // B_lo fragments, a_hi * b_lo
#pragma unroll
            for (int nj = 0; nj < 4; nj++)
                LDSM4(bb[nj][0], bb[nj][1], bb[nj][2], bb[nj][3], Bl + sw64(b_row[nj], cidx));
#pragma unroll
            for (int mi = 0; mi < 2; mi++)
#pragma unroll
                for (int nj = 0; nj < 4; nj++) {
                    MMA16816(acc[mi][nj*2+0], a[mi][0], a[mi][1], a[mi][2], a[mi][3], bb[nj][0], bb[nj][2]);
                    MMA16816(acc[mi][nj*2+1], a[mi][0], a[mi][1], a[mi][2], a[mi][3], bb[nj][1], bb[nj][3]);
                }
            // A_lo fragments, reload B_hi, a_lo * b_hi
#pragma unroll
            for (int mi = 0; mi < 2; mi++)
                LDSM4(a[mi][0], a[mi][1], a[mi][2], a[mi][3], Al + sw64(a_row[mi], cidx));
#pragma unroll
            for (int nj = 0; nj < 4; nj++)
                LDSM4(bb[nj][0], bb[nj][1], bb[nj][2], bb[nj][3], Bh + sw64(b_row[nj], cidx));
#pragma unroll
            for (int mi = 0; mi < 2; mi++)
#pragma unroll
                for (int nj = 0; nj < 4; nj++) {
                    MMA16816(acc[mi][nj*2+0], a[mi][0], a[mi][1], a[mi][2], a[mi][3], bb[nj][0], bb[nj][2]);
                    MMA16816(acc[mi][nj*2+1], a[mi][0], a[mi][1], a[mi][2], a[mi][3], bb[nj][1], bb[nj][3]);
                }
        }

        if (kt < 31) { STORE_A(kt + 1, buf ^ 1); CP_WAIT0(); }
        __syncthreads();
    }

    // ---- epilogue: tanh * v, reduce to s[n] ----
    float rs[2][2] = {{0.0f, 0.0f}, {0.0f, 0.0f}};
#pragma unroll
    for (int mi = 0; mi < 2; mi++)
#pragma unroll
        for (int hj = 0; hj < 8; hj++) {
            int hcol = whi * 64 + hj * 8 + (lane & 3) * 2;
            float v0 = vsm[hcol], v1 = vsm[hcol + 1];
            rs[mi][0] += ftanh(acc[mi][hj][0]) * v0 + ftanh(acc[mi][hj][1]) * v1;
            rs[mi][1] += ftanh(acc[mi][hj][2]) * v0 + ftanh(acc[mi][hj][3]) * v1;
        }
#pragma unroll
    for (int o = 1; o <= 2; o <<= 1) {
        rs[0][0] += __shfl_xor_sync(0xffffffffu, rs[0][0], o);
        rs[0][1] += __shfl_xor_sync(0xffffffffu, rs[0][1], o);
        rs[1][0] += __shfl_xor_sync(0xffffffffu, rs[1][0], o);
        rs[1][1] += __shfl_xor_sync(0xffffffffu, rs[1][1], o);
    }
    if ((lane & 3) == 0) {
        int r = wn * 32 + (lane >> 2);
        atomicAdd(&ssm[r],          rs[0][0]);
        atomicAdd(&ssm[r + 8],      rs[0][1]);
        atomicAdd(&ssm[r + 16],     rs[1][0]);
        atomicAdd(&ssm[r + 24],     rs[1][1]);
    }
    __syncthreads();
    if (t < 128)
        spart[(((size_t)b * NN + m) * 2 + hc) * NN + t] = ssm[t];
#undef ISSUE_B
#undef LOAD_X
#undef STORE_A
}

// ---------------------------------------------------------------------------
// Batched fp32 GEMM for the 5 projections (one launch).
// ---------------------------------------------------------------------------
__global__ __launch_bounds__(256) void gemm_batched(
    const float* __restrict__ x0, const float* __restrict__ x1,
    const float* __restrict__ Wc1, const float* __restrict__ Wc2,
    const float* __restrict__ Wm,  const float* __restrict__ Wb,
    float* __restrict__ S)
{
    const float* A; const float* W; float* C; int N;
    switch (blockIdx.z) {
        case 0: A = x0; W = Wc1; C = S + OFF_XC; N = HH; break;
        case 1: A = x1; W = Wc2; C = S + OFF_YC; N = HH; break;
        case 2: A = x0; W = Wm;  C = S + OFF_XM; N = HH; break;
        case 3: A = x1; W = Wm;  C = S + OFF_YM; N = HH; break;
        default: A = x0; W = Wb; C = S + OFF_XB; N = DD; break;
    }
    const int bn = blockIdx.x * 64;
    if (bn >= N) return;
    const int bm = blockIdx.y * 64;
    const int K = DD;

    __shared__ float As[16][68];
    __shared__ float Bs[16][68];
    const int t = threadIdx.x;
    const int tx = t & 15, ty = t >> 4;

    float acc[4][4];
#pragma unroll
    for (int i = 0; i < 4; i++)
#pragma unroll
        for (int j = 0; j < 4; j++) acc[i][j] = 0.0f;

    for (int k0 = 0; k0 < K; k0 += 16) {
#pragma unroll
        for (int i = 0; i < 4; i++) {
            int idx = t + i * 256;
            int r = idx >> 4, c = idx & 15;
            As[c][r] = A[(size_t)(bm + r) * K + k0 + c];
        }
#pragma unroll
        for (int i = 0; i < 4; i++) {
            int idx = t + i * 256;
            int r = idx >> 6, c = idx & 63;
            Bs[r][c] = W[(size_t)(k0 + r) * N + bn + c];
        }
        __syncthreads();
#pragma unroll
        for (int k = 0; k < 16; k++) {
            float a[4], bv[4];
#pragma unroll
            for (int i = 0; i < 4; i++) a[i] = As[k][ty * 4 + i];
#pragma unroll
            for (int j = 0; j < 4; j++) bv[j] = Bs[k][tx * 4 + j];
#pragma unroll
            for (int i = 0; i < 4; i++)
#pragma unroll
                for (int j = 0; j < 4; j++)
                    acc[i][j] = fmaf(a[i], bv[j], acc[i][j]);
        }
        __syncthreads();
    }
#pragma unroll
    for (int i = 0; i < 4; i++)
#pragma unroll
        for (int j = 0; j < 4; j++)
            C[(size_t)(bm + ty * 4 + i) * N + bn + tx * 4 + j] = acc[i][j];
}

// ---------------------------------------------------------------------------
// Concat/minus scores: s[b,m,n] = sum_h v_h * tanh(p[b,n,h] + sign*q[b,m,h])
// ---------------------------------------------------------------------------
__global__ __launch_bounds__(256) void pair_scores(
    const float* __restrict__ p, const float* __restrict__ q,
    const float* __restrict__ v, float* __restrict__ s, float sign)
{
    const int m = blockIdx.x, b = blockIdx.y;
    const int t = threadIdx.x, lane = t & 31, w = t >> 5;
    __shared__ float qs[HH], vs[HH];
    if (t < 128) {
        ((float4*)qs)[t] = ((const float4*)(q + ((size_t)b * NN + m) * HH))[t];
        ((float4*)vs)[t] = ((const float4*)v)[t];
    }
    __syncthreads();
    const float* pb = p + (size_t)b * NN * HH;
    for (int n = w; n < NN; n += 8) {
        const float* pr = pb + (size_t)n * HH;
        float acc = 0.0f;
#pragma unroll
        for (int h = 0; h < HH; h += 32) {
            int hh = h + lane;
            acc += vs[hh] * ftanh(fmaf(sign, qs[hh], pr[hh]));
        }
#pragma unroll
        for (int o = 16; o; o >>= 1) acc += __shfl_xor_sync(0xffffffffu, acc, o);
        if (lane == 0) s[((size_t)b * NN + m) * NN + n] = acc;
    }
}

// ---------------------------------------------------------------------------
// Bilinear scores: s[b,m,n] = sum_d x1[b,m,d] * xb[b,n,d]
// ---------------------------------------------------------------------------
__global__ __launch_bounds__(256) void bilin_scores(
    const float* __restrict__ y, const float* __restrict__ xb,
    float* __restrict__ s)
{
    const int m = blockIdx.x, b = blockIdx.y;
    const int t = threadIdx.x, lane = t & 31, w = t >> 5;
    __shared__ float ysm[DD];
    ((float4*)ysm)[t] = ((const float4*)(y + ((size_t)b * NN + m) * DD))[t];
    __syncthreads();
    const float* xbb = xb + (size_t)b * NN * DD;
    for (int n = w; n < NN; n += 8) {
        const float* xr = xbb + (size_t)n * DD;
        float acc = 0.0f;
#pragma unroll 8
        for (int d = lane; d < DD; d += 32) acc += ysm[d] * xr[d];
#pragma unroll
        for (int o = 16; o; o >>= 1) acc += __shfl_xor_sync(0xffffffffu, acc, o);
        if (lane == 0) s[((size_t)b * NN + m) * NN + n] = acc;
    }
}

// ---------------------------------------------------------------------------
// w1v[j] = sum_h Wp1[j,h] * vp[h]
// ---------------------------------------------------------------------------
__global__ void w1v_kernel(const float* __restrict__ Wp1,
                           const float* __restrict__ vp,
                           float* __restrict__ w1v)
{
    int j = blockIdx.x * 8 + (threadIdx.x >> 5);
    int lane = threadIdx.x & 31;
    const float* r = Wp1 + (size_t)j * HH;
    float acc = 0.0f;
#pragma unroll
    for (int h = lane; h < HH; h += 32) acc += r[h] * vp[h];
#pragma unroll
    for (int o = 16; o; o >>= 1) acc += __shfl_xor_sync(0xffffffffu, acc, o);
    if (lane == 0) w1v[j] = acc;
}

// ---------------------------------------------------------------------------
// Fused: 5 softmaxes + 5 weighted sums + max + agg_rep write.
// ---------------------------------------------------------------------------
__global__ __launch_bounds__(256) void fuse_att(
    const float* __restrict__ sc,  const float* __restrict__ sb,
    const float* __restrict__ smn, const float* __restrict__ sd1,
    const float* __restrict__ sd2,
    const float* __restrict__ x0,  const float* __restrict__ x1,
    float* __restrict__ aggrep)
{
    const int m = blockIdx.x, b = blockIdx.y;
    const int t = threadIdx.x, lane = t & 31, w = t >> 5;
    const size_t bm = (size_t)b * NN + m;
    __shared__ float aw[5][NN];

    if (t < 128) {
        aw[0][t] = sc [bm * NN + t];
        aw[1][t] = sb [bm * NN + t];
        aw[2][t] = smn[bm * NN + t];
        aw[3][t] = sd1[(bm * 2 + 0) * NN + t] + sd1[(bm * 2 + 1) * NN + t];
        aw[4][t] = sd2[(bm * 2 + 0) * NN + t] + sd2[(bm * 2 + 1) * NN + t];
    }
    __syncthreads();

    if (w < 5) {
        float v0 = aw[w][lane], v1 = aw[w][lane + 32];
        float v2 = aw[w][lane + 64], v3 = aw[w][lane + 96];
        float mx = fmaxf(fmaxf(v0, v1), fmaxf(v2, v3));
#pragma unroll
        for (int o = 16; o; o >>= 1) mx = fmaxf(mx, __shfl_xor_sync(0xffffffffu, mx, o));
        float e0 = __expf(v0 - mx), e1 = __expf(v1 - mx);
        float e2 = __expf(v2 - mx), e3 = __expf(v3 - mx);
        float sm = e0 + e1 + e2 + e3;
#pragma unroll
        for (int o = 16; o; o >>= 1) sm += __shfl_xor_sync(0xffffffffu, sm, o);
        float inv = 1.0f / sm;
        aw[w][lane]      = e0 * inv; aw[w][lane + 32] = e1 * inv;
        aw[w][lane + 64] = e2 * inv; aw[w][lane + 96] = e3 * inv;
    }
    __syncthreads();

    const int d = t * 4;
    float4 aC = {0,0,0,0}, aB = {0,0,0,0}, aS = {0,0,0,0}, aM = {0,0,0,0}, aD = {0,0,0,0};
    const float* x0b = x0 + (size_t)b * NN * DD;
    const float* x1b = x1 + (size_t)b * NN * DD;
    for (int n = 0; n < NN; n++) {
        float4 xv = *(const float4*)(x0b + (size_t)n * DD + d);
        float wc = aw[0][n], wb2 = aw[1][n], wm2 = aw[2][n], ws = aw[3][n];
        aC.x = fmaf(wc, xv.x, aC.x); aC.y = fmaf(wc, xv.y, aC.y);
        aC.z = fmaf(wc, xv.z, aC.z); aC.w = fmaf(wc, xv.w, aC.w);
        aB.x = fmaf(wb2, xv.x, aB.x); aB.y = fmaf(wb2, xv.y, aB.y);
        aB.z = fmaf(wb2, xv.z, aB.z); aB.w = fmaf(wb2, xv.w, aB.w);
        aM.x = fmaf(wm2, xv.x, aM.x); aM.y = fmaf(wm2, xv.y, aM.y);
        aM.z = fmaf(wm2, xv.z, aM.z); aM.w = fmaf(wm2, xv.w, aM.w);
        aS.x = fmaf(ws, xv.x, aS.x); aS.y = fmaf(ws, xv.y, aS.y);
        aS.z = fmaf(ws, xv.z, aS.z); aS.w = fmaf(ws, xv.w, aS.w);
        float4 yv = *(const float4*)(x1b + (size_t)n * DD + d);
        float wd = aw[4][n];
        aD.x = fmaf(wd, yv.x, aD.x); aD.y = fmaf(wd, yv.y, aD.y);
        aD.z = fmaf(wd, yv.z, aD.z); aD.w = fmaf(wd, yv.w, aD.w);
    }
    float4 xm1 = *(const float4*)(x1b + (size_t)m * DD + d);
    float4 ag;
    ag.x = fmaxf(xm1.x, fmaxf(fmaxf(aS.x, aC.x), fmaxf(fmaxf(aD.x, aB.x), aM.x)));
    ag.y = fmaxf(xm1.y, fmaxf(fmaxf(aS.y, aC.y), fmaxf(fmaxf(aD.y, aB.y), aM.y)));
    ag.z = fmaxf(xm1.z, fmaxf(fmaxf(aS.z, aC.z), fmaxf(fmaxf(aD.z, aB.z), aM.z)));
    ag.w = fmaxf(xm1.w, fmaxf(fmaxf(aS.w, aC.w), fmaxf(fmaxf(aD.w, aB.w), aM.w)));
    float* arow = aggrep + bm * (2 * DD);
    *(float4*)(arow + d)      = xm1;
    *(float4*)(arow + DD + d) = ag;
}

// ---------------------------------------------------------------------------
// Final head
// ---------------------------------------------------------------------------
__global__ __launch_bounds__(256) void final_kernel(
    const float* __restrict__ aggrep, const float* __restrict__ w1v,
    const float* __restrict__ Wpred,  const float* __restrict__ bpred,
    float* __restrict__ out)
{
    const int b = blockIdx.x;
    const int t = threadIdx.x, lane = t & 31, w = t >> 5;
    __shared__ float sp[NN];
    __shared__ float r0[8], r1[8];
    const float* ab = aggrep + (size_t)b * NN * (2 * DD);

    for (int mm = w; mm < NN; mm += 8) {
        const float* ar = ab + (size_t)mm * (2 * DD);
        float acc = 0.0f;
#pragma unroll
        for (int j = lane; j < 2 * DD; j += 32) acc += ar[j] * w1v[j];
#pragma unroll
        for (int o = 16; o; o >>= 1) acc += __shfl_xor_sync(0xffffffffu, acc, o);
        if (lane == 0) sp[mm] = acc;
    }
    __syncthreads();
    if (w == 0) {
        float v0 = sp[lane], v1 = sp[lane + 32], v2 = sp[lane + 64], v3 = sp[lane + 96];
        float mx = fmaxf(fmaxf(v0, v1), fmaxf(v2, v3));
#pragma unroll
        for (int o = 16; o; o >>= 1) mx = fmaxf(mx, __shfl_xor_sync(0xffffffffu, mx, o));
        float e0 = __expf(v0 - mx), e1 = __expf(v1 - mx);
        float e2 = __expf(v2 - mx), e3 = __expf(v3 - mx);
        float sm = e0 + e1 + e2 + e3;
#pragma unroll
        for (int o = 16; o; o >>= 1) sm += __shfl_xor_sync(0xffffffffu, sm, o);
        float inv = 1.0f / sm;
        sp[lane] = e0 * inv; sp[lane + 32] = e1 * inv;
        sp[lane + 64] = e2 * inv; sp[lane + 96] = e3 * inv;
    }
    __syncthreads();

    float rp[8];
#pragma unroll
    for (int k = 0; k < 8; k++) rp[k] = 0.0f;
    for (int mm = 0; mm < NN; mm++) {
        float wgt = sp[mm];
        const float* ar = ab + (size_t)mm * (2 * DD);
#pragma unroll
        for (int k = 0; k < 8; k++) rp[k] = fmaf(wgt, ar[t + k * 256], rp[k]);
    }
    float p0 = 0.0f, p1 = 0.0f;
#pragma unroll
    for (int k = 0; k < 8; k++) {
        int j = t + k * 256;
        p0 = fmaf(rp[k], Wpred[(size_t)j * 2 + 0], p0);
        p1 = fmaf(rp[k], Wpred[(size_t)j * 2 + 1], p1);
    }
#pragma unroll
    for (int o = 16; o; o >>= 1) {
        p0 += __shfl_xor_sync(0xffffffffu, p0, o);
        p1 += __shfl_xor_sync(0xffffffffu, p1, o);
    }
    if (lane == 0) { r0[w] = p0; r1[w] = p1; }
    __syncthreads();
    if (t == 0) {
        float s0 = 0.0f, s1 = 0.0f;
#pragma unroll
        for (int i = 0; i < 8; i++) { s0 += r0[i]; s1 += r1[i]; }
        out[b * 2 + 0] = fmaxf(s0 + bpred[0], 0.0f);
        out[b * 2 + 1] = fmaxf(s1 + bpred[1], 0.0f);
    }
}

// ---------------------------------------------------------------------------
extern "C" void kernel_launch(void* const* d_in, const int* in_sizes, int n_in,
                              void* d_out, int out_size)
{
    (void)in_sizes; (void)n_in; (void)out_size;
    float* S = nullptr;
    cudaGetSymbolAddress((void**)&S, g_scratch);
    __nv_bfloat16* WT = nullptr;
    cudaGetSymbolAddress((void**)&WT, g_wt);

    const float* x0    = (const float*)d_in[0];
    const float* x1    = (const float*)d_in[1];
    const float* Wc1   = (const float*)d_in[2];
    const float* Wc2   = (const float*)d_in[3];
    const float* vc    = (const float*)d_in[4];
    const float* Wb    = (const float*)d_in[5];
    const float* Wd1   = (const float*)d_in[6];
    const float* vd1   = (const float*)d_in[7];
    const float* Wd2   = (const float*)d_in[8];
    const float* vd2   = (const float*)d_in[9];
    const float* Wm    = (const float*)d_in[10];
    const float* vm    = (const float*)d_in[11];
    const float* Wp1   = (const float*)d_in[14];
    const float* vp    = (const float*)d_in[16];
    const float* Wpred = (const float*)d_in[17];
    const float* bpred = (const float*)d_in[18];
    float* out = (float*)d_out;

    cudaFuncSetAttribute(dot_scores_mma,
                         cudaFuncAttributeMaxDynamicSharedMemorySize, MSMEM);

    __nv_bfloat16* w1h = WT;
    __nv_bfloat16* w1l = WT + (size_t)HH * DD;
    __nv_bfloat16* w2h = WT + (size_t)2 * HH * DD;
    __nv_bfloat16* w2l = WT + (size_t)3 * HH * DD;

    // Weight prep (transpose + bf16 hi/lo split)
    wsplit_kernel<<<HH, 256>>>(Wd1, w1h, w1l);
    wsplit_kernel<<<HH, 256>>>(Wd2, w2h, w2l);
    w1v_kernel<<<256, 256>>>(Wp1, vp, S + OFF_W1V);

    // Projections (one batched launch)
    gemm_batched<<<dim3(16, 16, 5), 256>>>(x0, x1, Wc1, Wc2, Wm, Wb, S);

    // Dominant dot-attention scores on tensor cores (both attentions, one grid)
    dot_scores_mma<<<dim3(2, NN, 2 * BB), 512, MSMEM>>>(
        x0, x1, w1h, w1l, w2h, w2l, vd1, vd2, S + OFF_SD1, S + OFF_SD2);

    // Remaining scores
    pair_scores<<<dim3(NN, BB), 256>>>(S + OFF_XC, S + OFF_YC, vc, S + OFF_SC,  1.0f);
    pair_scores<<<dim3(NN, BB), 256>>>(S + OFF_XM, S + OFF_YM, vm, S + OFF_SMN, -1.0f);
    bilin_scores<<<dim3(NN, BB), 256>>>(x1, S + OFF_XB, S + OFF_SB);

    // Fused softmax/weighted-sum/max + final head
    fuse_att<<<dim3(NN, BB), 256>>>(S + OFF_SC, S + OFF_SB, S + OFF_SMN,
                                    S + OFF_SD1, S + OFF_SD2, x0, x1, S + OFF_AGG);
    final_kernel<<<BB, 256>>>(S + OFF_AGG, S + OFF_W1V, Wpred, bpred, out);
}

// round 5
// speedup vs baseline: 4.2030x; 1.8704x over previous
#include <cuda_runtime.h>
#include <cuda_fp16.h>
#include <cstdint>
#include <cstddef>

// ---------------------------------------------------------------------------
// Problem constants: B=8, N=M=128, H=512, D=2H=1024
// ---------------------------------------------------------------------------
#define BB   8
#define NN   128
#define HH   512
#define DD   1024

// Scratch layout (floats)
#define SZ_PROJ (BB*NN*HH)
#define SZ_XB   (BB*NN*DD)
#define SZ_S    (BB*NN*NN)
#define SZ_SD   (BB*NN*2*NN)
#define SZ_AGG  (BB*NN*2*DD)

#define OFF_XC  0
#define OFF_YC  (OFF_XC + SZ_PROJ)
#define OFF_XM  (OFF_YC + SZ_PROJ)
#define OFF_YM  (OFF_XM + SZ_PROJ)
#define OFF_XB  (OFF_YM + SZ_PROJ)
#define OFF_SC  (OFF_XB + SZ_XB)
#define OFF_SB  (OFF_SC + SZ_S)
#define OFF_SMN (OFF_SB + SZ_S)
#define OFF_SD1 (OFF_SMN + SZ_S)
#define OFF_SD2 (OFF_SD1 + SZ_SD)
#define OFF_AGG (OFF_SD2 + SZ_SD)
#define OFF_W1V (OFF_AGG + SZ_AGG)
#define SCRATCH_TOTAL (OFF_W1V + 2*DD)

__device__ float g_scratch[SCRATCH_TOTAL];
// fp16 W^T for the two dot attentions: [2][512*1024]
__device__ __half g_wth[2 * HH * DD];

// tanh(x) = 1 - 2/(exp(2x)+1)  (exact to ~1e-7; keeps the fp16 risk isolated)
__device__ __forceinline__ float ftanh(float x) {
    float e = __expf(2.0f * x);
    return 1.0f - __fdividef(2.0f, e + 1.0f);
}

__device__ __forceinline__ uint32_t smem_u32(const void* p) {
    uint32_t a;
    asm("{ .reg .u64 t; cvta.to.shared.u64 t, %1; cvt.u32.u64 %0, t; }" : "=r"(a) : "l"(p));
    return a;
}

#define LDSM4(r0, r1, r2, r3, addr) \
    asm volatile("ldmatrix.sync.aligned.m8n8.x4.shared.b16 {%0,%1,%2,%3}, [%4];" \
        : "=r"(r0), "=r"(r1), "=r"(r2), "=r"(r3) : "r"(addr))

#define MMA16816(d, a0, a1, a2, a3, b0, b1) \
    asm volatile("mma.sync.aligned.m16n8k16.row.col.f32.f16.f16.f32 " \
        "{%0,%1,%2,%3}, {%4,%5,%6,%7}, {%8,%9}, {%0,%1,%2,%3};" \
        : "+f"((d)[0]), "+f"((d)[1]), "+f"((d)[2]), "+f"((d)[3]) \
        : "r"(a0), "r"(a1), "r"(a2), "r"(a3), "r"(b0), "r"(b1))

#define CP_ASYNC16(sa, ga) \
    asm volatile("cp.async.cg.shared.global [%0], [%1], 16;" :: "r"(sa), "l"(ga))
#define CP_COMMIT() asm volatile("cp.async.commit_group;")
#define CP_WAIT0()  asm volatile("cp.async.wait_group 0;")

// 64B-row swizzle: byte ^ ((byte>>3)&0x30)
__device__ __forceinline__ uint32_t sw64(uint32_t row, uint32_t chunk) {
    return row * 64u + ((chunk * 16u) ^ ((row & 6u) << 3));
}

// ---------------------------------------------------------------------------
// W^T fp16:  wt[h*1024 + d] = (half)W[d*512 + h]
// ---------------------------------------------------------------------------
__global__ void wcvt_kernel(const float* __restrict__ W, __half* __restrict__ wt)
{
    int h = blockIdx.x;
#pragma unroll
    for (int i = 0; i < 4; i++) {
        int d = threadIdx.x + i * 256;
        wt[(size_t)h * DD + d] = __float2half_rn(W[(size_t)d * HH + h]);
    }
}

// ---------------------------------------------------------------------------
// mma.sync fp16 single-product dot-attention scores.
// CTA per (hc in 0..1, m in 0..127, z = b*2+att). 512 threads, 16 warps.
// CTA tile: 128(n) x 256(h), K=1024 in kc=32 chunks, double-buffered.
//   z[n,h] = sum_d (x[n,d]*y[m,d]) * W[d,h]
//   spart[bm][hc][n] = sum_{h in chunk} v_h * tanh(z[n,h])
// ---------------------------------------------------------------------------
// Dynamic SMEM layout (bytes)
#define MOFF_Y  0            // 4096  (y row, 1024 f32)
#define MOFF_V  4096         // 1024  (v chunk, 256 f32)
#define MOFF_S  5120         // 512   (s reduction, 128 f32)
#define MOFF_A  8192         // A[buf]: 2 x 8192  -> ends 24576
#define MOFF_B  24576        // B[buf]: 2 x 16384 -> ends 57344
#define MSMEM   57344

__global__ __launch_bounds__(512, 1) void dot_scores_mma(
    const float* __restrict__ x0, const float* __restrict__ x1,
    const __half* __restrict__ w1t, const __half* __restrict__ w2t,
    const float* __restrict__ vd1, const float* __restrict__ vd2,
    float* __restrict__ sp1, float* __restrict__ sp2)
{
    extern __shared__ char smc[];
    const uint32_t sb = smem_u32(smc);

    const int hc  = blockIdx.x;           // 0..1   (h chunk of 256)
    const int m   = blockIdx.y;           // 0..127
    const int att = blockIdx.z & 1;
    const int b   = blockIdx.z >> 1;

    const float* x = att ? x1 : x0;
    const float* y = att ? x0 : x1;
    const __half* wt = att ? w2t : w1t;
    const float* v = att ? vd2 : vd1;
    float* spart = att ? sp2 : sp1;

    const int t = threadIdx.x;
    const int lane = t & 31, wid = t >> 5;
    const int wn = wid & 3, whi = wid >> 2;       // warp n-group, h-group
    const int lane15 = lane & 15, lhalf = lane >> 4;

    float* ysm = (float*)(smc + MOFF_Y);
    float* vsm = (float*)(smc + MOFF_V);
    float* ssm = (float*)(smc + MOFF_S);

    // preload y row, v chunk, zero s
    ((float2*)ysm)[t] = ((const float2*)(y + ((size_t)b * NN + m) * DD))[t];
    if (t < 64) ((float4*)vsm)[t] = ((const float4*)(v + hc * 256))[t];
    if (t < 128) ssm[t] = 0.0f;

    const float* xg = x + (size_t)b * NN * DD;
    const __half* wg = wt + (size_t)(hc * 256) * DD;

    // per-thread tile coords
    const int an = t >> 2;                 // A row (n), 0..127
    const int ac = t & 3;                  // A 16B-chunk
    const uint32_t a_st = sw64(an, ac);    // A store offset
    const int br = t >> 2;                 // B row (first half), 0..127
    const int bc = t & 3;
    const uint32_t b_st0 = sw64(br, bc);
    const uint32_t b_st1 = b_st0 + 128 * 64;   // rows +128, same swizzle xor

    float xa0, xa1, xa2, xa3, xb0, xb1, xb2, xb3;   // staged x (8 floats)

#define ISSUE_B(kt, buf) do { \
        int k0_ = (kt) * 32; \
        const __half* bp_ = wg + (size_t)br * DD + k0_ + bc * 8; \
        uint32_t Bh_ = sb + MOFF_B + (buf) * 16384u; \
        CP_ASYNC16(Bh_ + b_st0, bp_); \
        CP_ASYNC16(Bh_ + b_st1, bp_ + 128 * DD); \
        CP_COMMIT(); \
    } while (0)

#define LOAD_X(kt) do { \
        int k0_ = (kt) * 32; \
        const float* xp_ = xg + (size_t)an * DD + k0_ + ac * 8; \
        float4 u_ = *(const float4*)xp_; \
        float4 w_ = *(const float4*)(xp_ + 4); \
        xa0 = u_.x; xa1 = u_.y; xa2 = u_.z; xa3 = u_.w; \
        xb0 = w_.x; xb1 = w_.y; xb2 = w_.z; xb3 = w_.w; \
    } while (0)

#define STORE_A(kt, buf) do { \
        int kb_ = (kt) * 32 + ac * 8; \
        union { __half h[8]; uint4 q; } u_; \
        u_.h[0] = __float2half_rn(xa0 * ysm[kb_ + 0]); \
        u_.h[1] = __float2half_rn(xa1 * ysm[kb_ + 1]); \
        u_.h[2] = __float2half_rn(xa2 * ysm[kb_ + 2]); \
        u_.h[3] = __float2half_rn(xa3 * ysm[kb_ + 3]); \
        u_.h[4] = __float2half_rn(xb0 * ysm[kb_ + 4]); \
        u_.h[5] = __float2half_rn(xb1 * ysm[kb_ + 5]); \
        u_.h[6] = __float2half_rn(xb2 * ysm[kb_ + 6]); \
        u_.h[7] = __float2half_rn(xb3 * ysm[kb_ + 7]); \
        *(uint4*)(smc + MOFF_A + (buf) * 8192 + a_st) = u_.q; \
    } while (0)

    float acc[2][8][4];
#pragma unroll
    for (int i = 0; i < 2; i++)
#pragma unroll
        for (int j = 0; j < 8; j++)
#pragma unroll
            for (int k = 0; k < 4; k++) acc[i][j][k] = 0.0f;

    // prologue: fill buffer 0
    ISSUE_B(0, 0);
    LOAD_X(0);
    __syncthreads();            // ysm ready before STORE_A uses it
    STORE_A(0, 0);
    CP_WAIT0();
    __syncthreads();

    // precomputed ldmatrix row offsets
    uint32_t a_row[2], b_row[4];
#pragma unroll
    for (int mi = 0; mi < 2; mi++) a_row[mi] = wn * 32 + mi * 16 + lane15;
#pragma unroll
    for (int nj = 0; nj < 4; nj++) b_row[nj] = whi * 64 + nj * 16 + lane15;

    for (int kt = 0; kt < 32; kt++) {
        const int buf = kt & 1;
        if (kt < 31) { ISSUE_B(kt + 1, buf ^ 1); LOAD_X(kt + 1); }

        const uint32_t Ah = sb + MOFF_A + buf * 8192u;
        const uint32_t Bh = sb + MOFF_B + buf * 16384u;

#pragma unroll
        for (int ks = 0; ks < 2; ks++) {
            const uint32_t cidx = ks * 2 + lhalf;
            uint32_t a[2][4], bb[4][4];
#pragma unroll
            for (int mi = 0; mi < 2; mi++)
                LDSM4(a[mi][0], a[mi][1], a[mi][2], a[mi][3], Ah + sw64(a_row[mi], cidx));
#pragma unroll
            for (int nj = 0; nj < 4; nj++)
                LDSM4(bb[nj][0], bb[nj][1], bb[nj][2], bb[nj][3], Bh + sw64(b_row[nj], cidx));
#pragma unroll
            for (int mi = 0; mi < 2; mi++)
#pragma unroll
                for (int nj = 0; nj < 4; nj++) {
                    MMA16816(acc[mi][nj*2+0], a[mi][0], a[mi][1], a[mi][2], a[mi][3], bb[nj][0], bb[nj][2]);
                    MMA16816(acc[mi][nj*2+1], a[mi][0], a[mi][1], a[mi][2], a[mi][3], bb[nj][1], bb[nj][3]);
                }
        }

        if (kt < 31) { STORE_A(kt + 1, buf ^ 1); CP_WAIT0(); }
        __syncthreads();
    }

    // ---- epilogue: tanh * v, reduce to s[n] ----
    float rs[2][2] = {{0.0f, 0.0f}, {0.0f, 0.0f}};
#pragma unroll
    for (int mi = 0; mi < 2; mi++)
#pragma unroll
        for (int hj = 0; hj < 8; hj++) {
            int hcol = whi * 64 + hj * 8 + (lane & 3) * 2;
            float v0 = vsm[hcol], v1 = vsm[hcol + 1];
            rs[mi][0] += ftanh(acc[mi][hj][0]) * v0 + ftanh(acc[mi][hj][1]) * v1;
            rs[mi][1] += ftanh(acc[mi][hj][2]) * v0 + ftanh(acc[mi][hj][3]) * v1;
        }
#pragma unroll
    for (int o = 1; o <= 2; o <<= 1) {
        rs[0][0] += __shfl_xor_sync(0xffffffffu, rs[0][0], o);
        rs[0][1] += __shfl_xor_sync(0xffffffffu, rs[0][1], o);
        rs[1][0] += __shfl_xor_sync(0xffffffffu, rs[1][0], o);
        rs[1][1] += __shfl_xor_sync(0xffffffffu, rs[1][1], o);
    }
    if ((lane & 3) == 0) {
        int r = wn * 32 + (lane >> 2);
        atomicAdd(&ssm[r],          rs[0][0]);
        atomicAdd(&ssm[r + 8],      rs[0][1]);
        atomicAdd(&ssm[r + 16],     rs[1][0]);
        atomicAdd(&ssm[r + 24],     rs[1][1]);
    }
    __syncthreads();
    if (t < 128)
        spart[(((size_t)b * NN + m) * 2 + hc) * NN + t] = ssm[t];
#undef ISSUE_B
#undef LOAD_X
#undef STORE_A
}

// ---------------------------------------------------------------------------
// Batched fp32 GEMM for the 5 projections (one launch).
// ---------------------------------------------------------------------------
__global__ __launch_bounds__(256) void gemm_batched(
    const float* __restrict__ x0, const float* __restrict__ x1,
    const float* __restrict__ Wc1, const float* __restrict__ Wc2,
    const float* __restrict__ Wm,  const float* __restrict__ Wb,
    float* __restrict__ S)
{
    const float* A; const float* W; float* C; int N;
    switch (blockIdx.z) {
        case 0: A = x0; W = Wc1; C = S + OFF_XC; N = HH; break;
        case 1: A = x1; W = Wc2; C = S + OFF_YC; N = HH; break;
        case 2: A = x0; W = Wm;  C = S + OFF_XM; N = HH; break;
        case 3: A = x1; W = Wm;  C = S + OFF_YM; N = HH; break;
        default: A = x0; W = Wb; C = S + OFF_XB; N = DD; break;
    }
    const int bn = blockIdx.x * 64;
    if (bn >= N) return;
    const int bm = blockIdx.y * 64;
    const int K = DD;

    __shared__ float As[16][68];
    __shared__ float Bs[16][68];
    const int t = threadIdx.x;
    const int tx = t & 15, ty = t >> 4;

    float acc[4][4];
#pragma unroll
    for (int i = 0; i < 4; i++)
#pragma unroll
        for (int j = 0; j < 4; j++) acc[i][j] = 0.0f;

    for (int k0 = 0; k0 < K; k0 += 16) {
#pragma unroll
        for (int i = 0; i < 4; i++) {
            int idx = t + i * 256;
            int r = idx >> 4, c = idx & 15;
            As[c][r] = A[(size_t)(bm + r) * K + k0 + c];
        }
#pragma unroll
        for (int i = 0; i < 4; i++) {
            int idx = t + i * 256;
            int r = idx >> 6, c = idx & 63;
            Bs[r][c] = W[(size_t)(k0 + r) * N + bn + c];
        }
        __syncthreads();
#pragma unroll
        for (int k = 0; k < 16; k++) {
            float a[4], bv[4];
#pragma unroll
            for (int i = 0; i < 4; i++) a[i] = As[k][ty * 4 + i];
#pragma unroll
            for (int j = 0; j < 4; j++) bv[j] = Bs[k][tx * 4 + j];
#pragma unroll
            for (int i = 0; i < 4; i++)
#pragma unroll
                for (int j = 0; j < 4; j++)
                    acc[i][j] = fmaf(a[i], bv[j], acc[i][j]);
        }
        __syncthreads();
    }
#pragma unroll
    for (int i = 0; i < 4; i++)
#pragma unroll
        for (int j = 0; j < 4; j++)
            C[(size_t)(bm + ty * 4 + i) * N + bn + tx * 4 + j] = acc[i][j];
}

// ---------------------------------------------------------------------------
// Concat/minus scores: s[b,m,n] = sum_h v_h * tanh(p[b,n,h] + sign*q[b,m,h])
// ---------------------------------------------------------------------------
__global__ __launch_bounds__(256) void pair_scores(
    const float* __restrict__ p, const float* __restrict__ q,
    const float* __restrict__ v, float* __restrict__ s, float sign)
{
    const int m = blockIdx.x, b = blockIdx.y;
    const int t = threadIdx.x, lane = t & 31, w = t >> 5;
    __shared__ float qs[HH], vs[HH];
    if (t < 128) {
        ((float4*)qs)[t] = ((const float4*)(q + ((size_t)b * NN + m) * HH))[t];
        ((float4*)vs)[t] = ((const float4*)v)[t];
    }
    __syncthreads();
    const float* pb = p + (size_t)b * NN * HH;
    for (int n = w; n < NN; n += 8) {
        const float* pr = pb + (size_t)n * HH;
        float acc = 0.0f;
#pragma unroll
        for (int h = 0; h < HH; h += 32) {
            int hh = h + lane;
            acc += vs[hh] * ftanh(fmaf(sign, qs[hh], pr[hh]));
        }
#pragma unroll
        for (int o = 16; o; o >>= 1) acc += __shfl_xor_sync(0xffffffffu, acc, o);
        if (lane == 0) s[((size_t)b * NN + m) * NN + n] = acc;
    }
}

// ---------------------------------------------------------------------------
// Bilinear scores: s[b,m,n] = sum_d x1[b,m,d] * xb[b,n,d]
// ---------------------------------------------------------------------------
__global__ __launch_bounds__(256) void bilin_scores(
    const float* __restrict__ y, const float* __restrict__ xb,
    float* __restrict__ s)
{
    const int m = blockIdx.x, b = blockIdx.y;
    const int t = threadIdx.x, lane = t & 31, w = t >> 5;
    __shared__ float ysm[DD];
    ((float4*)ysm)[t] = ((const float4*)(y + ((size_t)b * NN + m) * DD))[t];
    __syncthreads();
    const float* xbb = xb + (size_t)b * NN * DD;
    for (int n = w; n < NN; n += 8) {
        const float* xr = xbb + (size_t)n * DD;
        float acc = 0.0f;
#pragma unroll 8
        for (int d = lane; d < DD; d += 32) acc += ysm[d] * xr[d];
#pragma unroll
        for (int o = 16; o; o >>= 1) acc += __shfl_xor_sync(0xffffffffu, acc, o);
        if (lane == 0) s[((size_t)b * NN + m) * NN + n] = acc;
    }
}

// ---------------------------------------------------------------------------
// w1v[j] = sum_h Wp1[j,h] * vp[h]
// ---------------------------------------------------------------------------
__global__ void w1v_kernel(const float* __restrict__ Wp1,
                           const float* __restrict__ vp,
                           float* __restrict__ w1v)
{
    int j = blockIdx.x * 8 + (threadIdx.x >> 5);
    int lane = threadIdx.x & 31;
    const float* r = Wp1 + (size_t)j * HH;
    float acc = 0.0f;
#pragma unroll
    for (int h = lane; h < HH; h += 32) acc += r[h] * vp[h];
#pragma unroll
    for (int o = 16; o; o >>= 1) acc += __shfl_xor_sync(0xffffffffu, acc, o);
    if (lane == 0) w1v[j] = acc;
}

// ---------------------------------------------------------------------------
// Fused: 5 softmaxes + 5 weighted sums + max + agg_rep write.
// ---------------------------------------------------------------------------
__global__ __launch_bounds__(256) void fuse_att(
    const float* __restrict__ sc,  const float* __restrict__ sb,
    const float* __restrict__ smn, const float* __restrict__ sd1,
    const float* __restrict__ sd2,
    const float* __restrict__ x0,  const float* __restrict__ x1,
    float* __restrict__ aggrep)
{
    const int m = blockIdx.x, b = blockIdx.y;
    const int t = threadIdx.x, lane = t & 31, w = t >> 5;
    const size_t bm = (size_t)b * NN + m;
    __shared__ float aw[5][NN];

    if (t < 128) {
        aw[0][t] = sc [bm * NN + t];
        aw[1][t] = sb [bm * NN + t];
        aw[2][t] = smn[bm * NN + t];
        aw[3][t] = sd1[(bm * 2 + 0) * NN + t] + sd1[(bm * 2 + 1) * NN + t];
        aw[4][t] = sd2[(bm * 2 + 0) * NN + t] + sd2[(bm * 2 + 1) * NN + t];
    }
    __syncthreads();

    if (w < 5) {
        float v0 = aw[w][lane], v1 = aw[w][lane + 32];
        float v2 = aw[w][lane + 64], v3 = aw[w][lane + 96];
        float mx = fmaxf(fmaxf(v0, v1), fmaxf(v2, v3));
#pragma unroll
        for (int o = 16; o; o >>= 1) mx = fmaxf(mx, __shfl_xor_sync(0xffffffffu, mx, o));
        float e0 = __expf(v0 - mx), e1 = __expf(v1 - mx);
        float e2 = __expf(v2 - mx), e3 = __expf(v3 - mx);
        float sm = e0 + e1 + e2 + e3;
#pragma unroll
        for (int o = 16; o; o >>= 1) sm += __shfl_xor_sync(0xffffffffu, sm, o);
        float inv = 1.0f / sm;
        aw[w][lane]      = e0 * inv; aw[w][lane + 32] = e1 * inv;
        aw[w][lane + 64] = e2 * inv; aw[w][lane + 96] = e3 * inv;
    }
    __syncthreads();

    const int d = t * 4;
    float4 aC = {0,0,0,0}, aB = {0,0,0,0}, aS = {0,0,0,0}, aM = {0,0,0,0}, aD = {0,0,0,0};
    const float* x0b = x0 + (size_t)b * NN * DD;
    const float* x1b = x1 + (size_t)b * NN * DD;
    for (int n = 0; n < NN; n++) {
        float4 xv = *(const float4*)(x0b + (size_t)n * DD + d);
        float wc = aw[0][n], wb2 = aw[1][n], wm2 = aw[2][n], ws = aw[3][n];
        aC.x = fmaf(wc, xv.x, aC.x); aC.y = fmaf(wc, xv.y, aC.y);
        aC.z = fmaf(wc, xv.z, aC.z); aC.w = fmaf(wc, xv.w, aC.w);
        aB.x = fmaf(wb2, xv.x, aB.x); aB.y = fmaf(wb2, xv.y, aB.y);
        aB.z = fmaf(wb2, xv.z, aB.z); aB.w = fmaf(wb2, xv.w, aB.w);
        aM.x = fmaf(wm2, xv.x, aM.x); aM.y = fmaf(wm2, xv.y, aM.y);
        aM.z = fmaf(wm2, xv.z, aM.z); aM.w = fmaf(wm2, xv.w, aM.w);
        aS.x = fmaf(ws, xv.x, aS.x); aS.y = fmaf(ws, xv.y, aS.y);
        aS.z = fmaf(ws, xv.z, aS.z); aS.w = fmaf(ws, xv.w, aS.w);
        float4 yv = *(const float4*)(x1b + (size_t)n * DD + d);
        float wd = aw[4][n];
        aD.x = fmaf(wd, yv.x, aD.x); aD.y = fmaf(wd, yv.y, aD.y);
        aD.z = fmaf(wd, yv.z, aD.z); aD.w = fmaf(wd, yv.w, aD.w);
    }
    float4 xm1 = *(const float4*)(x1b + (size_t)m * DD + d);
    float4 ag;
    ag.x = fmaxf(xm1.x, fmaxf(fmaxf(aS.x, aC.x), fmaxf(fmaxf(aD.x, aB.x), aM.x)));
    ag.y = fmaxf(xm1.y, fmaxf(fmaxf(aS.y, aC.y), fmaxf(fmaxf(aD.y, aB.y), aM.y)));
    ag.z = fmaxf(xm1.z, fmaxf(fmaxf(aS.z, aC.z), fmaxf(fmaxf(aD.z, aB.z), aM.z)));
    ag.w = fmaxf(xm1.w, fmaxf(fmaxf(aS.w, aC.w), fmaxf(fmaxf(aD.w, aB.w), aM.w)));
    float* arow = aggrep + bm * (2 * DD);
    *(float4*)(arow + d)      = xm1;
    *(float4*)(arow + DD + d) = ag;
}

// ---------------------------------------------------------------------------
// Final head
// ---------------------------------------------------------------------------
__global__ __launch_bounds__(256) void final_kernel(
    const float* __restrict__ aggrep, const float* __restrict__ w1v,
    const float* __restrict__ Wpred,  const float* __restrict__ bpred,
    float* __restrict__ out)
{
    const int b = blockIdx.x;
    const int t = threadIdx.x, lane = t & 31, w = t >> 5;
    __shared__ float sp[NN];
    __shared__ float r0[8], r1[8];
    const float* ab = aggrep + (size_t)b * NN * (2 * DD);

    for (int mm = w; mm < NN; mm += 8) {
        const float* ar = ab + (size_t)mm * (2 * DD);
        float acc = 0.0f;
#pragma unroll
        for (int j = lane; j < 2 * DD; j += 32) acc += ar[j] * w1v[j];
#pragma unroll
        for (int o = 16; o; o >>= 1) acc += __shfl_xor_sync(0xffffffffu, acc, o);
        if (lane == 0) sp[mm] = acc;
    }
    __syncthreads();
    if (w == 0) {
        float v0 = sp[lane], v1 = sp[lane + 32], v2 = sp[lane + 64], v3 = sp[lane + 96];
        float mx = fmaxf(fmaxf(v0, v1), fmaxf(v2, v3));
#pragma unroll
        for (int o = 16; o; o >>= 1) mx = fmaxf(mx, __shfl_xor_sync(0xffffffffu, mx, o));
        float e0 = __expf(v0 - mx), e1 = __expf(v1 - mx);
        float e2 = __expf(v2 - mx), e3 = __expf(v3 - mx);
        float sm = e0 + e1 + e2 + e3;
#pragma unroll
        for (int o = 16; o; o >>= 1) sm += __shfl_xor_sync(0xffffffffu, sm, o);
        float inv = 1.0f / sm;
        sp[lane] = e0 * inv; sp[lane + 32] = e1 * inv;
        sp[lane + 64] = e2 * inv; sp[lane + 96] = e3 * inv;
    }
    __syncthreads();

    float rp[8];
#pragma unroll
    for (int k = 0; k < 8; k++) rp[k] = 0.0f;
    for (int mm = 0; mm < NN; mm++) {
        float wgt = sp[mm];
        const float* ar = ab + (size_t)mm * (2 * DD);
#pragma unroll
        for (int k = 0; k < 8; k++) rp[k] = fmaf(wgt, ar[t + k * 256], rp[k]);
    }
    float p0 = 0.0f, p1 = 0.0f;
#pragma unroll
    for (int k = 0; k < 8; k++) {
        int j = t + k * 256;
        p0 = fmaf(rp[k], Wpred[(size_t)j * 2 + 0], p0);
        p1 = fmaf(rp[k], Wpred[(size_t)j * 2 + 1], p1);
    }
#pragma unroll
    for (int o = 16; o; o >>= 1) {
        p0 += __shfl_xor_sync(0xffffffffu, p0, o);
        p1 += __shfl_xor_sync(0xffffffffu, p1, o);
    }
    if (lane == 0) { r0[w] = p0; r1[w] = p1; }
    __syncthreads();
    if (t == 0) {
        float s0 = 0.0f, s1 = 0.0f;
#pragma unroll
        for (int i = 0; i < 8; i++) { s0 += r0[i]; s1 += r1[i]; }
        out[b * 2 + 0] = fmaxf(s0 + bpred[0], 0.0f);
        out[b * 2 + 1] = fmaxf(s1 + bpred[1], 0.0f);
    }
}

// ---------------------------------------------------------------------------
extern "C" void kernel_launch(void* const* d_in, const int* in_sizes, int n_in,
                              void* d_out, int out_size)
{
    (void)in_sizes; (void)n_in; (void)out_size;
    float* S = nullptr;
    cudaGetSymbolAddress((void**)&S, g_scratch);
    __half* WT = nullptr;
    cudaGetSymbolAddress((void**)&WT, g_wth);

    const float* x0    = (const float*)d_in[0];
    const float* x1    = (const float*)d_in[1];
    const float* Wc1   = (const float*)d_in[2];
    const float* Wc2   = (const float*)d_in[3];
    const float* vc    = (const float*)d_in[4];
    const float* Wb    = (const float*)d_in[5];
    const float* Wd1   = (const float*)d_in[6];
    const float* vd1   = (const float*)d_in[7];
    const float* Wd2   = (const float*)d_in[8];
    const float* vd2   = (const float*)d_in[9];
    const float* Wm    = (const float*)d_in[10];
    const float* vm    = (const float*)d_in[11];
    const float* Wp1   = (const float*)d_in[14];
    const float* vp    = (const float*)d_in[16];
    const float* Wpred = (const float*)d_in[17];
    const float* bpred = (const float*)d_in[18];
    float* out = (float*)d_out;

    cudaFuncSetAttribute(dot_scores_mma,
                         cudaFuncAttributeMaxDynamicSharedMemorySize, MSMEM);

    __half* w1t = WT;
    __half* w2t = WT + (size_t)HH * DD;

    // Weight prep (transpose + fp16 convert)
    wcvt_kernel<<<HH, 256>>>(Wd1, w1t);
    wcvt_kernel<<<HH, 256>>>(Wd2, w2t);
    w1v_kernel<<<256, 256>>>(Wp1, vp, S + OFF_W1V);

    // Projections (one batched launch)
    gemm_batched<<<dim3(16, 16, 5), 256>>>(x0, x1, Wc1, Wc2, Wm, Wb, S);

    // Dominant dot-attention scores on tensor cores (both attentions, one grid)
    dot_scores_mma<<<dim3(2, NN, 2 * BB), 512, MSMEM>>>(
        x0, x1, w1t, w2t, vd1, vd2, S + OFF_SD1, S + OFF_SD2);

    // Remaining scores
    pair_scores<<<dim3(NN, BB), 256>>>(S + OFF_XC, S + OFF_YC, vc, S + OFF_SC,  1.0f);
    pair_scores<<<dim3(NN, BB), 256>>>(S + OFF_XM, S + OFF_YM, vm, S + OFF_SMN, -1.0f);
    bilin_scores<<<dim3(NN, BB), 256>>>(x1, S + OFF_XB, S + OFF_SB);

    // Fused softmax/weighted-sum/max + final head
    fuse_att<<<dim3(NN, BB), 256>>>(S + OFF_SC, S + OFF_SB, S + OFF_SMN,
                                    S + OFF_SD1, S + OFF_SD2, x0, x1, S + OFF_AGG);
    final_kernel<<<BB, 256>>>(S + OFF_AGG, S + OFF_W1V, Wpred, bpred, out);
}

// round 6
// speedup vs baseline: 4.8046x; 1.1431x over previous
#include <cuda_runtime.h>
#include <cuda_fp16.h>
#include <cstdint>
#include <cstddef>

// ---------------------------------------------------------------------------
// Problem constants: B=8, N=M=128, H=512, D=2H=1024
// ---------------------------------------------------------------------------
#define BB   8
#define NN   128
#define HH   512
#define DD   1024

// Scratch layout (floats)
#define SZ_PROJ (BB*NN*HH)
#define SZ_XB   (BB*NN*DD)
#define SZ_S    (BB*NN*NN)
#define SZ_SD   (BB*NN*2*NN)
#define SZ_AGG  (BB*NN*2*DD)

#define OFF_XC  0
#define OFF_YC  (OFF_XC + SZ_PROJ)
#define OFF_XM  (OFF_YC + SZ_PROJ)
#define OFF_YM  (OFF_XM + SZ_PROJ)
#define OFF_XB  (OFF_YM + SZ_PROJ)
#define OFF_SC  (OFF_XB + SZ_XB)
#define OFF_SB  (OFF_SC + SZ_S)
#define OFF_SMN (OFF_SB + SZ_S)
#define OFF_SD1 (OFF_SMN + SZ_S)
#define OFF_SD2 (OFF_SD1 + SZ_SD)
#define OFF_AGG (OFF_SD2 + SZ_SD)
#define OFF_W1V (OFF_AGG + SZ_AGG)
#define SCRATCH_TOTAL (OFF_W1V + 2*DD)

__device__ float g_scratch[SCRATCH_TOTAL];

// fp16 pool: dot W^T x2, x0/x1, proj W^T x4
#define HW1 0
#define HW2 (HW1 + HH*DD)
#define HX0 (HW2 + HH*DD)
#define HX1 (HX0 + NN*BB*DD)
#define HC1 (HX1 + NN*BB*DD)
#define HC2 (HC1 + HH*DD)
#define HM  (HC2 + HH*DD)
#define HB  (HM  + HH*DD)
#define HALF_TOTAL (HB + DD*DD)
__device__ __align__(16) __half g_half[HALF_TOTAL];

// tanh via MUFU.TANH (abs err ~6e-4; same order as fp16 product noise)
__device__ __forceinline__ float ftanh(float x) {
    float y;
    asm("tanh.approx.f32 %0, %1;" : "=f"(y) : "f"(x));
    return y;
}

__device__ __forceinline__ uint32_t smem_u32(const void* p) {
    uint32_t a;
    asm("{ .reg .u64 t; cvta.to.shared.u64 t, %1; cvt.u32.u64 %0, t; }" : "=r"(a) : "l"(p));
    return a;
}

#define LDSM4(r0, r1, r2, r3, addr) \
    asm volatile("ldmatrix.sync.aligned.m8n8.x4.shared.b16 {%0,%1,%2,%3}, [%4];" \
        : "=r"(r0), "=r"(r1), "=r"(r2), "=r"(r3) : "r"(addr))

#define MMA16816(d, a0, a1, a2, a3, b0, b1) \
    asm volatile("mma.sync.aligned.m16n8k16.row.col.f32.f16.f16.f32 " \
        "{%0,%1,%2,%3}, {%4,%5,%6,%7}, {%8,%9}, {%0,%1,%2,%3};" \
        : "+f"((d)[0]), "+f"((d)[1]), "+f"((d)[2]), "+f"((d)[3]) \
        : "r"(a0), "r"(a1), "r"(a2), "r"(a3), "r"(b0), "r"(b1))

#define CP_ASYNC16(sa, ga) \
    asm volatile("cp.async.cg.shared.global [%0], [%1], 16;" :: "r"(sa), "l"(ga))
#define CP_COMMIT() asm volatile("cp.async.commit_group;")
#define CP_WAIT0()  asm volatile("cp.async.wait_group 0;")

// 128B-row swizzle (8 chunks of 16B): chunk ^= row&7
__device__ __forceinline__ uint32_t sw128(uint32_t row, uint32_t chunk) {
    return row * 128u + ((chunk * 16u) ^ ((row & 7u) << 4));
}

// ---------------------------------------------------------------------------
// W^T fp16:  wt[h*DD + d] = (half)W[d*N + h]    (transpose + convert)
// ---------------------------------------------------------------------------
__global__ void wcvt_kernel(const float* __restrict__ W, __half* __restrict__ wt, int N)
{
    int h = blockIdx.x;
#pragma unroll
    for (int i = 0; i < 4; i++) {
        int d = threadIdx.x + i * 256;
        wt[(size_t)h * DD + d] = __float2half_rn(W[(size_t)d * N + h]);
    }
}

// x fp32 -> fp16 elementwise (1,048,576 elements; grid 1024 x 256 x 4)
__global__ void xcvt_kernel(const float* __restrict__ x, __half* __restrict__ xh)
{
    int i = blockIdx.x * 1024 + threadIdx.x * 4;
    float4 v = *(const float4*)(x + i);
    __half2* o = (__half2*)(xh + i);
    o[0] = __floats2half2_rn(v.x, v.y);
    o[1] = __floats2half2_rn(v.z, v.w);
}

// ---------------------------------------------------------------------------
// mma.sync fp16 dot-attention scores. CTA per (hc, m, b*2+att). 512 thr/16 warps.
// CTA tile 128(n) x 256(h); K=1024 in kc=64 chunks, double-buffered.
// ---------------------------------------------------------------------------
#define MOFF_Y  0            // 4096
#define MOFF_V  4096         // 1024
#define MOFF_S  5120         // 512
#define MOFF_A  8192         // 2 x 16384 -> 40960
#define MOFF_B  40960        // 2 x 32768 -> 106496
#define MSMEM   106496

__global__ __launch_bounds__(512, 1) void dot_scores_mma(
    const float* __restrict__ x0, const float* __restrict__ x1,
    const __half* __restrict__ w1t, const __half* __restrict__ w2t,
    const float* __restrict__ vd1, const float* __restrict__ vd2,
    float* __restrict__ sp1, float* __restrict__ sp2)
{
    extern __shared__ char smc[];
    const uint32_t sb = smem_u32(smc);

    const int hc  = blockIdx.x;
    const int m   = blockIdx.y;
    const int att = blockIdx.z & 1;
    const int b   = blockIdx.z >> 1;

    const float* x = att ? x1 : x0;
    const float* y = att ? x0 : x1;
    const __half* wt = att ? w2t : w1t;
    const float* v = att ? vd2 : vd1;
    float* spart = att ? sp2 : sp1;

    const int t = threadIdx.x;
    const int lane = t & 31, wid = t >> 5;
    const int wn = wid & 3, whi = wid >> 2;
    const int lane15 = lane & 15, lhalf = lane >> 4;

    float* ysm = (float*)(smc + MOFF_Y);
    float* vsm = (float*)(smc + MOFF_V);
    float* ssm = (float*)(smc + MOFF_S);

    ((float2*)ysm)[t] = ((const float2*)(y + ((size_t)b * NN + m) * DD))[t];
    if (t < 64) ((float4*)vsm)[t] = ((const float4*)(v + hc * 256))[t];
    if (t < 128) ssm[t] = 0.0f;

    const float* xg = x + (size_t)b * NN * DD;
    const __half* wg = wt + (size_t)(hc * 256) * DD;

    // A tile (128 x 64 fp16, 128B rows): an = t>>2 (0..127), chunks {ac, ac+4}
    const int an = t >> 2, ac = t & 3;
    const uint32_t a_st0 = sw128(an, ac);
    const uint32_t a_st1 = sw128(an, ac + 4);
    // B tile (256 x 64 fp16): br = t>>1 (0..255), chunks bc*4..bc*4+3
    const int br = t >> 1, bc4 = (t & 1) * 4;
    uint32_t b_st[4];
#pragma unroll
    for (int j = 0; j < 4; j++) b_st[j] = sw128(br, bc4 + j);

    float xs[16];   // staged x (2 chunks x 8)

#define ISSUE_B(kt, buf) do { \
        const __half* bp_ = wg + (size_t)br * DD + (kt) * 64 + bc4 * 8; \
        uint32_t Bb_ = sb + MOFF_B + (buf) * 32768u; \
        CP_ASYNC16(Bb_ + b_st[0], bp_); \
        CP_ASYNC16(Bb_ + b_st[1], bp_ + 8); \
        CP_ASYNC16(Bb_ + b_st[2], bp_ + 16); \
        CP_ASYNC16(Bb_ + b_st[3], bp_ + 24); \
        CP_COMMIT(); \
    } while (0)

#define LOAD_X(kt) do { \
        const float* xp_ = xg + (size_t)an * DD + (kt) * 64 + ac * 8; \
        *(float4*)&xs[0]  = *(const float4*)xp_; \
        *(float4*)&xs[4]  = *(const float4*)(xp_ + 4); \
        *(float4*)&xs[8]  = *(const float4*)(xp_ + 32); \
        *(float4*)&xs[12] = *(const float4*)(xp_ + 36); \
    } while (0)

#define STORE_A(kt, buf) do { \
        int kb_ = (kt) * 64 + ac * 8; \
        union { __half h[8]; uint4 q; } u0_, u1_; \
        _Pragma("unroll") \
        for (int j_ = 0; j_ < 8; j_++) { \
            u0_.h[j_] = __float2half_rn(xs[j_]     * ysm[kb_ + j_]); \
            u1_.h[j_] = __float2half_rn(xs[j_ + 8] * ysm[kb_ + 32 + j_]); \
        } \
        char* Ab_ = smc + MOFF_A + (buf) * 16384; \
        *(uint4*)(Ab_ + a_st0) = u0_.q; \
        *(uint4*)(Ab_ + a_st1) = u1_.q; \
    } while (0)

    float acc[2][8][4];
#pragma unroll
    for (int i = 0; i < 2; i++)
#pragma unroll
        for (int j = 0; j < 8; j++)
#pragma unroll
            for (int k = 0; k < 4; k++) acc[i][j][k] = 0.0f;

    ISSUE_B(0, 0);
    LOAD_X(0);
    __syncthreads();
    STORE_A(0, 0);
    CP_WAIT0();
    __syncthreads();

    uint32_t a_row[2], b_row[4];
#pragma unroll
    for (int mi = 0; mi < 2; mi++) a_row[mi] = wn * 32 + mi * 16 + lane15;
#pragma unroll
    for (int nj = 0; nj < 4; nj++) b_row[nj] = whi * 64 + nj * 16 + lane15;

    for (int kt = 0; kt < 16; kt++) {
        const int buf = kt & 1;
        if (kt < 15) { ISSUE_B(kt + 1, buf ^ 1); LOAD_X(kt + 1); }

        const uint32_t Ah = sb + MOFF_A + buf * 16384u;
        const uint32_t Bh = sb + MOFF_B + buf * 32768u;

#pragma unroll
        for (int ks = 0; ks < 4; ks++) {
            const uint32_t cidx = ks * 2 + lhalf;
            uint32_t a[2][4], bb[4][4];
#pragma unroll
            for (int mi = 0; mi < 2; mi++)
                LDSM4(a[mi][0], a[mi][1], a[mi][2], a[mi][3], Ah + sw128(a_row[mi], cidx));
#pragma unroll
            for (int nj = 0; nj < 4; nj++)
                LDSM4(bb[nj][0], bb[nj][1], bb[nj][2], bb[nj][3], Bh + sw128(b_row[nj], cidx));
#pragma unroll
            for (int mi = 0; mi < 2; mi++)
#pragma unroll
                for (int nj = 0; nj < 4; nj++) {
                    MMA16816(acc[mi][nj*2+0], a[mi][0], a[mi][1], a[mi][2], a[mi][3], bb[nj][0], bb[nj][2]);
                    MMA16816(acc[mi][nj*2+1], a[mi][0], a[mi][1], a[mi][2], a[mi][3], bb[nj][1], bb[nj][3]);
                }
        }

        if (kt < 15) { STORE_A(kt + 1, buf ^ 1); CP_WAIT0(); }
        __syncthreads();
    }

    // epilogue: tanh * v, reduce to s[n]
    float rs[2][2] = {{0.0f, 0.0f}, {0.0f, 0.0f}};
#pragma unroll
    for (int mi = 0; mi < 2; mi++)
#pragma unroll
        for (int hj = 0; hj < 8; hj++) {
            int hcol = whi * 64 + hj * 8 + (lane & 3) * 2;
            float v0 = vsm[hcol], v1 = vsm[hcol + 1];
            rs[mi][0] += ftanh(acc[mi][hj][0]) * v0 + ftanh(acc[mi][hj][1]) * v1;
            rs[mi][1] += ftanh(acc[mi][hj][2]) * v0 + ftanh(acc[mi][hj][3]) * v1;
        }
#pragma unroll
    for (int o = 1; o <= 2; o <<= 1) {
        rs[0][0] += __shfl_xor_sync(0xffffffffu, rs[0][0], o);
        rs[0][1] += __shfl_xor_sync(0xffffffffu, rs[0][1], o);
        rs[1][0] += __shfl_xor_sync(0xffffffffu, rs[1][0], o);
        rs[1][1] += __shfl_xor_sync(0xffffffffu, rs[1][1], o);
    }
    if ((lane & 3) == 0) {
        int r = wn * 32 + (lane >> 2);
        atomicAdd(&ssm[r],      rs[0][0]);
        atomicAdd(&ssm[r + 8],  rs[0][1]);
        atomicAdd(&ssm[r + 16], rs[1][0]);
        atomicAdd(&ssm[r + 24], rs[1][1]);
    }
    __syncthreads();
    if (t < 128)
        spart[(((size_t)b * NN + m) * 2 + hc) * NN + t] = ssm[t];
#undef ISSUE_B
#undef LOAD_X
#undef STORE_A
}

// ---------------------------------------------------------------------------
// fp16 mma projections: C[M,N] = A[M,K] @ W[K,N] with A fp16 [M,K], WT fp16 [N,K].
// CTA 256 thr / 8 warps, tile 128m x 128n, kc=64 double-buffered.
// grid (8, 8, 5); z<4: N=512 (bx>=4 exit), z=4: N=1024.
// ---------------------------------------------------------------------------
#define POFF_A 0
#define POFF_B 32768
#define PSMEM  65536

__global__ __launch_bounds__(256, 1) void proj_mma(
    const __half* __restrict__ xh0, const __half* __restrict__ xh1,
    const __half* __restrict__ wc1t, const __half* __restrict__ wc2t,
    const __half* __restrict__ wmt,  const __half* __restrict__ wbt,
    float* __restrict__ S)
{
    const __half* A; const __half* W; float* C; int N;
    switch (blockIdx.z) {
        case 0: A = xh0; W = wc1t; C = S + OFF_XC; N = HH; break;
        case 1: A = xh1; W = wc2t; C = S + OFF_YC; N = HH; break;
        case 2: A = xh0; W = wmt;  C = S + OFF_XM; N = HH; break;
        case 3: A = xh1; W = wmt;  C = S + OFF_YM; N = HH; break;
        default: A = xh0; W = wbt; C = S + OFF_XB; N = DD; break;
    }
    const int bn = blockIdx.x * 128;
    if (bn >= N) return;
    const int bm = blockIdx.y * 128;

    extern __shared__ char smc[];
    const uint32_t sb = smem_u32(smc);
    const int t = threadIdx.x, lane = t & 31, wid = t >> 5;
    const int wm = wid & 3, whn = wid >> 2;
    const int lane15 = lane & 15, lhalf = lane >> 4;

    const int r = t >> 1, cc4 = (t & 1) * 4;
    uint32_t st_off[4];
#pragma unroll
    for (int j = 0; j < 4; j++) st_off[j] = sw128(r, cc4 + j);
    const __half* ag = A + (size_t)(bm + r) * DD + cc4 * 8;
    const __half* wgp = W + (size_t)(bn + r) * DD + cc4 * 8;

#define P_ISSUE(kt, buf) do { \
        uint32_t Ab_ = sb + POFF_A + (buf) * 16384u; \
        uint32_t Bb_ = sb + POFF_B + (buf) * 16384u; \
        const __half* ap_ = ag + (kt) * 64; \
        const __half* bp_ = wgp + (kt) * 64; \
        _Pragma("unroll") \
        for (int j_ = 0; j_ < 4; j_++) { \
            CP_ASYNC16(Ab_ + st_off[j_], ap_ + j_ * 8); \
            CP_ASYNC16(Bb_ + st_off[j_], bp_ + j_ * 8); \
        } \
        CP_COMMIT(); \
    } while (0)

    float acc[2][8][4];
#pragma unroll
    for (int i = 0; i < 2; i++)
#pragma unroll
        for (int j = 0; j < 8; j++)
#pragma unroll
            for (int k = 0; k < 4; k++) acc[i][j][k] = 0.0f;

    P_ISSUE(0, 0);
    CP_WAIT0();
    __syncthreads();

    uint32_t a_row[2], b_row[4];
#pragma unroll
    for (int mi = 0; mi < 2; mi++) a_row[mi] = wm * 32 + mi * 16 + lane15;
#pragma unroll
    for (int nj = 0; nj < 4; nj++) b_row[nj] = whn * 64 + nj * 16 + lane15;

    for (int kt = 0; kt < 16; kt++) {
        const int buf = kt & 1;
        if (kt < 15) P_ISSUE(kt + 1, buf ^ 1);

        const uint32_t Ah = sb + POFF_A + buf * 16384u;
        const uint32_t Bh = sb + POFF_B + buf * 16384u;

#pragma unroll
        for (int ks = 0; ks < 4; ks++) {
            const uint32_t cidx = ks * 2 + lhalf;
            uint32_t a[2][4], bb[4][4];
#pragma unroll
            for (int mi = 0; mi < 2; mi++)
                LDSM4(a[mi][0], a[mi][1], a[mi][2], a[mi][3], Ah + sw128(a_row[mi], cidx));
#pragma unroll
            for (int nj = 0; nj < 4; nj++)
                LDSM4(bb[nj][0], bb[nj][1], bb[nj][2], bb[nj][3], Bh + sw128(b_row[nj], cidx));
#pragma unroll
            for (int mi = 0; mi < 2; mi++)
#pragma unroll
                for (int nj = 0; nj < 4; nj++) {
                    MMA16816(acc[mi][nj*2+0], a[mi][0], a[mi][1], a[mi][2], a[mi][3], bb[nj][0], bb[nj][2]);
                    MMA16816(acc[mi][nj*2+1], a[mi][0], a[mi][1], a[mi][2], a[mi][3], bb[nj][1], bb[nj][3]);
                }
        }

        CP_WAIT0();
        __syncthreads();
    }

    // epilogue: write fp32 C
#pragma unroll
    for (int mi = 0; mi < 2; mi++) {
        int row = bm + wm * 32 + mi * 16 + (lane >> 2);
#pragma unroll
        for (int nj8 = 0; nj8 < 8; nj8++) {
            int col = bn + whn * 64 + nj8 * 8 + (lane & 3) * 2;
            C[(size_t)row * N + col]           = acc[mi][nj8][0];
            C[(size_t)row * N + col + 1]       = acc[mi][nj8][1];
            C[(size_t)(row + 8) * N + col]     = acc[mi][nj8][2];
            C[(size_t)(row + 8) * N + col + 1] = acc[mi][nj8][3];
        }
    }
#undef P_ISSUE
}

// ---------------------------------------------------------------------------
// Concat/minus scores: s[b,m,n] = sum_h v_h * tanh(p[b,n,h] + sign*q[b,m,h])
// ---------------------------------------------------------------------------
__global__ __launch_bounds__(256) void pair_scores(
    const float* __restrict__ p, const float* __restrict__ q,
    const float* __restrict__ v, float* __restrict__ s, float sign)
{
    const int m = blockIdx.x, b = blockIdx.y;
    const int t = threadIdx.x, lane = t & 31, w = t >> 5;
    __shared__ float qs[HH], vs[HH];
    if (t < 128) {
        ((float4*)qs)[t] = ((const float4*)(q + ((size_t)b * NN + m) * HH))[t];
        ((float4*)vs)[t] = ((const float4*)v)[t];
    }
    __syncthreads();
    const float* pb = p + (size_t)b * NN * HH;
    for (int n = w; n < NN; n += 8) {
        const float* pr = pb + (size_t)n * HH;
        float acc = 0.0f;
#pragma unroll
        for (int h = 0; h < HH; h += 32) {
            int hh = h + lane;
            acc += vs[hh] * ftanh(fmaf(sign, qs[hh], pr[hh]));
        }
#pragma unroll
        for (int o = 16; o; o >>= 1) acc += __shfl_xor_sync(0xffffffffu, acc, o);
        if (lane == 0) s[((size_t)b * NN + m) * NN + n] = acc;
    }
}

// ---------------------------------------------------------------------------
// Bilinear scores: s[b,m,n] = sum_d x1[b,m,d] * xb[b,n,d]
// ---------------------------------------------------------------------------
__global__ __launch_bounds__(256) void bilin_scores(
    const float* __restrict__ y, const float* __restrict__ xb,
    float* __restrict__ s)
{
    const int m = blockIdx.x, b = blockIdx.y;
    const int t = threadIdx.x, lane = t & 31, w = t >> 5;
    __shared__ float ysm[DD];
    ((float4*)ysm)[t] = ((const float4*)(y + ((size_t)b * NN + m) * DD))[t];
    __syncthreads();
    const float* xbb = xb + (size_t)b * NN * DD;
    for (int n = w; n < NN; n += 8) {
        const float* xr = xbb + (size_t)n * DD;
        float acc = 0.0f;
#pragma unroll 8
        for (int d = lane; d < DD; d += 32) acc += ysm[d] * xr[d];
#pragma unroll
        for (int o = 16; o; o >>= 1) acc += __shfl_xor_sync(0xffffffffu, acc, o);
        if (lane == 0) s[((size_t)b * NN + m) * NN + n] = acc;
    }
}

// ---------------------------------------------------------------------------
// w1v[j] = sum_h Wp1[j,h] * vp[h]
// ---------------------------------------------------------------------------
__global__ void w1v_kernel(const float* __restrict__ Wp1,
                           const float* __restrict__ vp,
                           float* __restrict__ w1v)
{
    int j = blockIdx.x * 8 + (threadIdx.x >> 5);
    int lane = threadIdx.x & 31;
    const float* r = Wp1 + (size_t)j * HH;
    float acc = 0.0f;
#pragma unroll
    for (int h = lane; h < HH; h += 32) acc += r[h] * vp[h];
#pragma unroll
    for (int o = 16; o; o >>= 1) acc += __shfl_xor_sync(0xffffffffu, acc, o);
    if (lane == 0) w1v[j] = acc;
}

// ---------------------------------------------------------------------------
// Fused: 5 softmaxes + 5 weighted sums + max + agg_rep write.
// ---------------------------------------------------------------------------
__global__ __launch_bounds__(256) void fuse_att(
    const float* __restrict__ sc,  const float* __restrict__ sb,
    const float* __restrict__ smn, const float* __restrict__ sd1,
    const float* __restrict__ sd2,
    const float* __restrict__ x0,  const float* __restrict__ x1,
    float* __restrict__ aggrep)
{
    const int m = blockIdx.x, b = blockIdx.y;
    const int t = threadIdx.x, lane = t & 31, w = t >> 5;
    const size_t bm = (size_t)b * NN + m;
    __shared__ float aw[5][NN];

    if (t < 128) {
        aw[0][t] = sc [bm * NN + t];
        aw[1][t] = sb [bm * NN + t];
        aw[2][t] = smn[bm * NN + t];
        aw[3][t] = sd1[(bm * 2 + 0) * NN + t] + sd1[(bm * 2 + 1) * NN + t];
        aw[4][t] = sd2[(bm * 2 + 0) * NN + t] + sd2[(bm * 2 + 1) * NN + t];
    }
    __syncthreads();

    if (w < 5) {
        float v0 = aw[w][lane], v1 = aw[w][lane + 32];
        float v2 = aw[w][lane + 64], v3 = aw[w][lane + 96];
        float mx = fmaxf(fmaxf(v0, v1), fmaxf(v2, v3));
#pragma unroll
        for (int o = 16; o; o >>= 1) mx = fmaxf(mx, __shfl_xor_sync(0xffffffffu, mx, o));
        float e0 = __expf(v0 - mx), e1 = __expf(v1 - mx);
        float e2 = __expf(v2 - mx), e3 = __expf(v3 - mx);
        float sm = e0 + e1 + e2 + e3;
#pragma unroll
        for (int o = 16; o; o >>= 1) sm += __shfl_xor_sync(0xffffffffu, sm, o);
        float inv = 1.0f / sm;
        aw[w][lane]      = e0 * inv; aw[w][lane + 32] = e1 * inv;
        aw[w][lane + 64] = e2 * inv; aw[w][lane + 96] = e3 * inv;
    }
    __syncthreads();

    const int d = t * 4;
    float4 aC = {0,0,0,0}, aB = {0,0,0,0}, aS = {0,0,0,0}, aM = {0,0,0,0}, aD = {0,0,0,0};
    const float* x0b = x0 + (size_t)b * NN * DD;
    const float* x1b = x1 + (size_t)b * NN * DD;
    for (int n = 0; n < NN; n++) {
        float4 xv = *(const float4*)(x0b + (size_t)n * DD + d);
        float wc = aw[0][n], wb2 = aw[1][n], wm2 = aw[2][n], ws = aw[3][n];
        aC.x = fmaf(wc, xv.x, aC.x); aC.y = fmaf(wc, xv.y, aC.y);
        aC.z = fmaf(wc, xv.z, aC.z); aC.w = fmaf(wc, xv.w, aC.w);
        aB.x = fmaf(wb2, xv.x, aB.x); aB.y = fmaf(wb2, xv.y, aB.y);
        aB.z = fmaf(wb2, xv.z, aB.z); aB.w = fmaf(wb2, xv.w, aB.w);
        aM.x = fmaf(wm2, xv.x, aM.x); aM.y = fmaf(wm2, xv.y, aM.y);
        aM.z = fmaf(wm2, xv.z, aM.z); aM.w = fmaf(wm2, xv.w, aM.w);
        aS.x = fmaf(ws, xv.x, aS.x); aS.y = fmaf(ws, xv.y, aS.y);
        aS.z = fmaf(ws, xv.z, aS.z); aS.w = fmaf(ws, xv.w, aS.w);
        float4 yv = *(const float4*)(x1b + (size_t)n * DD + d);
        float wd = aw[4][n];
        aD.x = fmaf(wd, yv.x, aD.x); aD.y = fmaf(wd, yv.y, aD.y);
        aD.z = fmaf(wd, yv.z, aD.z); aD.w = fmaf(wd, yv.w, aD.w);
    }
    float4 xm1 = *(const float4*)(x1b + (size_t)m * DD + d);
    float4 ag;
    ag.x = fmaxf(xm1.x, fmaxf(fmaxf(aS.x, aC.x), fmaxf(fmaxf(aD.x, aB.x), aM.x)));
    ag.y = fmaxf(xm1.y, fmaxf(fmaxf(aS.y, aC.y), fmaxf(fmaxf(aD.y, aB.y), aM.y)));
    ag.z = fmaxf(xm1.z, fmaxf(fmaxf(aS.z, aC.z), fmaxf(fmaxf(aD.z, aB.z), aM.z)));
    ag.w = fmaxf(xm1.w, fmaxf(fmaxf(aS.w, aC.w), fmaxf(fmaxf(aD.w, aB.w), aM.w)));
    float* arow = aggrep + bm * (2 * DD);
    *(float4*)(arow + d)      = xm1;
    *(float4*)(arow + DD + d) = ag;
}

// ---------------------------------------------------------------------------
// Final head
// ---------------------------------------------------------------------------
__global__ __launch_bounds__(256) void final_kernel(
    const float* __restrict__ aggrep, const float* __restrict__ w1v,
    const float* __restrict__ Wpred,  const float* __restrict__ bpred,
    float* __restrict__ out)
{
    const int b = blockIdx.x;
    const int t = threadIdx.x, lane = t & 31, w = t >> 5;
    __shared__ float sp[NN];
    __shared__ float r0[8], r1[8];
    const float* ab = aggrep + (size_t)b * NN * (2 * DD);

    for (int mm = w; mm < NN; mm += 8) {
        const float* ar = ab + (size_t)mm * (2 * DD);
        float acc = 0.0f;
#pragma unroll
        for (int j = lane; j < 2 * DD; j += 32) acc += ar[j] * w1v[j];
#pragma unroll
        for (int o = 16; o; o >>= 1) acc += __shfl_xor_sync(0xffffffffu, acc, o);
        if (lane == 0) sp[mm] = acc;
    }
    __syncthreads();
    if (w == 0) {
        float v0 = sp[lane], v1 = sp[lane + 32], v2 = sp[lane + 64], v3 = sp[lane + 96];
        float mx = fmaxf(fmaxf(v0, v1), fmaxf(v2, v3));
#pragma unroll
        for (int o = 16; o; o >>= 1) mx = fmaxf(mx, __shfl_xor_sync(0xffffffffu, mx, o));
        float e0 = __expf(v0 - mx), e1 = __expf(v1 - mx);
        float e2 = __expf(v2 - mx), e3 = __expf(v3 - mx);
        float sm = e0 + e1 + e2 + e3;
#pragma unroll
        for (int o = 16; o; o >>= 1) sm += __shfl_xor_sync(0xffffffffu, sm, o);
        float inv = 1.0f / sm;
        sp[lane] = e0 * inv; sp[lane + 32] = e1 * inv;
        sp[lane + 64] = e2 * inv; sp[lane + 96] = e3 * inv;
    }
    __syncthreads();

    float rp[8];
#pragma unroll
    for (int k = 0; k < 8; k++) rp[k] = 0.0f;
    for (int mm = 0; mm < NN; mm++) {
        float wgt = sp[mm];
        const float* ar = ab + (size_t)mm * (2 * DD);
#pragma unroll
        for (int k = 0; k < 8; k++) rp[k] = fmaf(wgt, ar[t + k * 256], rp[k]);
    }
    float p0 = 0.0f, p1 = 0.0f;
#pragma unroll
    for (int k = 0; k < 8; k++) {
        int j = t + k * 256;
        p0 = fmaf(rp[k], Wpred[(size_t)j * 2 + 0], p0);
        p1 = fmaf(rp[k], Wpred[(size_t)j * 2 + 1], p1);
    }
#pragma unroll
    for (int o = 16; o; o >>= 1) {
        p0 += __shfl_xor_sync(0xffffffffu, p0, o);
        p1 += __shfl_xor_sync(0xffffffffu, p1, o);
    }
    if (lane == 0) { r0[w] = p0; r1[w] = p1; }
    __syncthreads();
    if (t == 0) {
        float s0 = 0.0f, s1 = 0.0f;
#pragma unroll
        for (int i = 0; i < 8; i++) { s0 += r0[i]; s1 += r1[i]; }
        out[b * 2 + 0] = fmaxf(s0 + bpred[0], 0.0f);
        out[b * 2 + 1] = fmaxf(s1 + bpred[1], 0.0f);
    }
}

// ---------------------------------------------------------------------------
extern "C" void kernel_launch(void* const* d_in, const int* in_sizes, int n_in,
                              void* d_out, int out_size)
{
    (void)in_sizes; (void)n_in; (void)out_size;
    float* S = nullptr;
    cudaGetSymbolAddress((void**)&S, g_scratch);
    __half* HP = nullptr;
    cudaGetSymbolAddress((void**)&HP, g_half);

    const float* x0    = (const float*)d_in[0];
    const float* x1    = (const float*)d_in[1];
    const float* Wc1   = (const float*)d_in[2];
    const float* Wc2   = (const float*)d_in[3];
    const float* vc    = (const float*)d_in[4];
    const float* Wb    = (const float*)d_in[5];
    const float* Wd1   = (const float*)d_in[6];
    const float* vd1   = (const float*)d_in[7];
    const float* Wd2   = (const float*)d_in[8];
    const float* vd2   = (const float*)d_in[9];
    const float* Wm    = (const float*)d_in[10];
    const float* vm    = (const float*)d_in[11];
    const float* Wp1   = (const float*)d_in[14];
    const float* vp    = (const float*)d_in[16];
    const float* Wpred = (const float*)d_in[17];
    const float* bpred = (const float*)d_in[18];
    float* out = (float*)d_out;

    cudaFuncSetAttribute(dot_scores_mma,
                         cudaFuncAttributeMaxDynamicSharedMemorySize, MSMEM);
    cudaFuncSetAttribute(proj_mma,
                         cudaFuncAttributeMaxDynamicSharedMemorySize, PSMEM);

    __half* w1t  = HP + HW1;
    __half* w2t  = HP + HW2;
    __half* xh0  = HP + HX0;
    __half* xh1  = HP + HX1;
    __half* wc1t = HP + HC1;
    __half* wc2t = HP + HC2;
    __half* wmt  = HP + HM;
    __half* wbt  = HP + HB;

    // Prep: transposed fp16 weights + fp16 inputs
    wcvt_kernel<<<HH, 256>>>(Wd1, w1t, HH);
    wcvt_kernel<<<HH, 256>>>(Wd2, w2t, HH);
    wcvt_kernel<<<HH, 256>>>(Wc1, wc1t, HH);
    wcvt_kernel<<<HH, 256>>>(Wc2, wc2t, HH);
    wcvt_kernel<<<HH, 256>>>(Wm,  wmt,  HH);
    wcvt_kernel<<<DD, 256>>>(Wb,  wbt,  DD);
    xcvt_kernel<<<1024, 256>>>(x0, xh0);
    xcvt_kernel<<<1024, 256>>>(x1, xh1);
    w1v_kernel<<<256, 256>>>(Wp1, vp, S + OFF_W1V);

    // Projections on tensor cores (one launch)
    proj_mma<<<dim3(8, 8, 5), 256, PSMEM>>>(xh0, xh1, wc1t, wc2t, wmt, wbt, S);

    // Dominant dot-attention scores on tensor cores (both attentions, one grid)
    dot_scores_mma<<<dim3(2, NN, 2 * BB), 512, MSMEM>>>(
        x0, x1, w1t, w2t, vd1, vd2, S + OFF_SD1, S + OFF_SD2);

    // Remaining scores
    pair_scores<<<dim3(NN, BB), 256>>>(S + OFF_XC, S + OFF_YC, vc, S + OFF_SC,  1.0f);
    pair_scores<<<dim3(NN, BB), 256>>>(S + OFF_XM, S + OFF_YM, vm, S + OFF_SMN, -1.0f);
    bilin_scores<<<dim3(NN, BB), 256>>>(x1, S + OFF_XB, S + OFF_SB);

    // Fused softmax/weighted-sum/max + final head
    fuse_att<<<dim3(NN, BB), 256>>>(S + OFF_SC, S + OFF_SB, S + OFF_SMN,
                                    S + OFF_SD1, S + OFF_SD2, x0, x1, S + OFF_AGG);
    final_kernel<<<BB, 256>>>(S + OFF_AGG, S + OFF_W1V, Wpred, bpred, out);
}